// round 13
// baseline (speedup 1.0000x reference)
#include <cuda_runtime.h>
#include <cuda_bf16.h>
#include <math_constants.h>
#include <cstdint>

// Problem constants (fixed by setup_inputs)
#define N1T   65536
#define N2T   16384
#define CIN   512
#define COUT  256
#define BN_EPS 1e-5f

// ---------------- scratch (device globals; no allocs allowed) --------------
__device__ float g_f2[N2T * COUT];            // linear2 output, fp32 (16 MB)
__device__ int   g_knn_idx[N1T * 3];
__device__ float g_knn_w[N1T * 3];
__device__ __nv_bfloat16 g_x1hi[N1T * COUT];  // feat_1 split
__device__ __nv_bfloat16 g_x1lo[N1T * COUT];
__device__ __nv_bfloat16 g_x2hi[N2T * CIN];   // feat_2 split
__device__ __nv_bfloat16 g_x2lo[N2T * CIN];
__device__ __nv_bfloat16 g_w1hi[COUT * COUT];
__device__ __nv_bfloat16 g_w1lo[COUT * COUT];
__device__ __nv_bfloat16 g_w2hi[COUT * CIN];
__device__ __nv_bfloat16 g_w2lo[COUT * CIN];

// ---------------- PTX helpers (baseline ISA only; NO tcgen05) --------------
__device__ __forceinline__ uint32_t smem_u32(const void* p) {
    uint32_t a;
    asm("{ .reg .u64 t; cvta.to.shared.u64 t, %1; cvt.u32.u64 %0, t; }"
        : "=r"(a) : "l"(p));
    return a;
}
__device__ __forceinline__ void cp16(uint32_t saddr, const void* g) {
    asm volatile("cp.async.cg.shared.global [%0], [%1], 16;"
                 :: "r"(saddr), "l"(g) : "memory");
}
__device__ __forceinline__ void cp_commit() {
    asm volatile("cp.async.commit_group;" ::: "memory");
}
template <int N>
__device__ __forceinline__ void cp_wait() {
    asm volatile("cp.async.wait_group %0;" :: "n"(N) : "memory");
}
__device__ __forceinline__ void ldsm4(uint32_t (&r)[4], uint32_t addr) {
    asm volatile("ldmatrix.sync.aligned.m8n8.x4.shared.b16 {%0,%1,%2,%3}, [%4];"
                 : "=r"(r[0]), "=r"(r[1]), "=r"(r[2]), "=r"(r[3]) : "r"(addr));
}
__device__ __forceinline__ void mma16816(float (&d)[4], const uint32_t (&a)[4],
                                         uint32_t b0, uint32_t b1) {
    asm volatile(
        "mma.sync.aligned.m16n8k16.row.col.f32.bf16.bf16.f32 "
        "{%0,%1,%2,%3}, {%4,%5,%6,%7}, {%8,%9}, {%0,%1,%2,%3};"
        : "+f"(d[0]), "+f"(d[1]), "+f"(d[2]), "+f"(d[3])
        : "r"(a[0]), "r"(a[1]), "r"(a[2]), "r"(a[3]), "r"(b0), "r"(b1));
}
// 64B-row XOR swizzle: conflict-free ldmatrix with 64B row stride
__device__ __forceinline__ uint32_t sw64(uint32_t off) {
    return off ^ ((off >> 3) & 0x30);
}

// ---------------------------------------------------------------------------
// Split fp32 -> (hi, lo) bf16 pair
// ---------------------------------------------------------------------------
__global__ void split_bf16_kernel(const float* __restrict__ in,
                                  __nv_bfloat16* __restrict__ hi,
                                  __nv_bfloat16* __restrict__ lo, int n4) {
    int i = blockIdx.x * blockDim.x + threadIdx.x;
    if (i >= n4) return;
    float4 v = reinterpret_cast<const float4*>(in)[i];
    float vv[4] = {v.x, v.y, v.z, v.w};
    ushort4 h, l;
    unsigned short* hp = &h.x;
    unsigned short* lp = &l.x;
    #pragma unroll
    for (int j = 0; j < 4; ++j) {
        __nv_bfloat16 hb = __float2bfloat16(vv[j]);
        __nv_bfloat16 lb = __float2bfloat16(vv[j] - __bfloat162float(hb));
        hp[j] = __bfloat16_as_ushort(hb);
        lp[j] = __bfloat16_as_ushort(lb);
    }
    reinterpret_cast<ushort4*>(hi)[i] = h;
    reinterpret_cast<ushort4*>(lo)[i] = l;
}

// ---------------------------------------------------------------------------
// KNN: bit-exact d2 arithmetic (load-bearing for rel_err — do not change):
//   qq = (qx*qx + qy*qy) + qz*qz ; pp likewise
//   dot = fma(qz,pz, fma(qy,py, qx*px)) ; d2 = (qq+pp) - 2*dot
// Strict-< insertion keeps lower index on ties (matches jax.lax.top_k).
// Grid: (64, 4) — one thread per query of its segment.
// ---------------------------------------------------------------------------
#define KNN_CHUNK 2048

struct Top3 {
    float d0, d1, d2;
    int i0, i1, i2;
};

__device__ __forceinline__ void knn_point(Top3& t3, const float4 p, int gj,
                                          float qx, float qy, float qz, float qq) {
    const float dot = fmaf(qz, p.z, fmaf(qy, p.y, __fmul_rn(qx, p.x)));
    const float t = __fsub_rn(__fadd_rn(qq, p.w), __fmul_rn(2.0f, dot));
    if (t < t3.d2) {
        if (t < t3.d1) {
            t3.d2 = t3.d1; t3.i2 = t3.i1;
            if (t < t3.d0) { t3.d1 = t3.d0; t3.i1 = t3.i0; t3.d0 = t; t3.i0 = gj; }
            else           { t3.d1 = t; t3.i1 = gj; }
        } else { t3.d2 = t; t3.i2 = gj; }
    }
}

__global__ void knn_kernel(const float* __restrict__ pts1,
                           const int*   __restrict__ rs1,
                           const float* __restrict__ pts2,
                           const int*   __restrict__ rs2) {
    __shared__ float4 sp[KNN_CHUNK];

    const int seg = blockIdx.y;
    const int tid = threadIdx.x;
    const int q_start = rs1[seg], q_end = rs1[seg + 1];
    const int p_start = rs2[seg], p_end = rs2[seg + 1];
    const int nq = q_end - q_start;
    const int np = p_end - p_start;

    const int ql = blockIdx.x * blockDim.x + tid;
    const bool active = ql < nq;
    const int q = q_start + (active ? ql : 0);

    const float qx = pts1[q * 3 + 0];
    const float qy = pts1[q * 3 + 1];
    const float qz = pts1[q * 3 + 2];
    const float qq = __fadd_rn(__fadd_rn(__fmul_rn(qx, qx), __fmul_rn(qy, qy)),
                               __fmul_rn(qz, qz));

    Top3 t3 = {CUDART_INF_F, CUDART_INF_F, CUDART_INF_F, 0, 0, 0};

    for (int cb = 0; cb < np; cb += KNN_CHUNK) {
        const int cnt = min(KNN_CHUNK, np - cb);
        __syncthreads();
        for (int j = tid; j < cnt; j += blockDim.x) {
            const int pi = p_start + cb + j;
            const float px = pts2[pi * 3 + 0];
            const float py = pts2[pi * 3 + 1];
            const float pz = pts2[pi * 3 + 2];
            const float pp = __fadd_rn(
                __fadd_rn(__fmul_rn(px, px), __fmul_rn(py, py)),
                __fmul_rn(pz, pz));
            sp[j] = make_float4(px, py, pz, pp);
        }
        __syncthreads();
        if (active) {
            if (cnt == KNN_CHUNK) {        // fast path: static trip count
                #pragma unroll 8
                for (int j = 0; j < KNN_CHUNK; ++j)
                    knn_point(t3, sp[j], cb + j, qx, qy, qz, qq);
            } else {
                for (int j = 0; j < cnt; ++j)
                    knn_point(t3, sp[j], cb + j, qx, qy, qz, qq);
            }
        }
    }

    if (active) {
        const float e0 = fmaxf(t3.d0, 0.f), e1 = fmaxf(t3.d1, 0.f), e2 = fmaxf(t3.d2, 0.f);
        const float w0 = 1.f / (e0 + 1e-8f);
        const float w1 = 1.f / (e1 + 1e-8f);
        const float w2 = 1.f / (e2 + 1e-8f);
        const float inv = 1.f / (w0 + w1 + w2);
        const int base = q * 3;
        g_knn_idx[base + 0] = p_start + t3.i0;  g_knn_w[base + 0] = w0 * inv;
        g_knn_idx[base + 1] = p_start + t3.i1;  g_knn_w[base + 1] = w1 * inv;
        g_knn_idx[base + 2] = p_start + t3.i2;  g_knn_w[base + 2] = w2 * inv;
    }
}

// ---------------------------------------------------------------------------
// interp_add: out[r, :] += w0*f2[j0,:] + w1*f2[j1,:] + w2*f2[j2,:]
// One warp per row; each lane covers 8 cols as 2 float4 slices.
// f2 (16 MB) is L2-resident; out streams through DRAM once (RMW).
// ---------------------------------------------------------------------------
__global__ void __launch_bounds__(256)
interp_add_kernel(float* __restrict__ out) {
    const int warp = (blockIdx.x * blockDim.x + threadIdx.x) >> 5;
    const int lane = threadIdx.x & 31;
    const int b3 = warp * 3;
    const int j0 = g_knn_idx[b3 + 0];
    const int j1 = g_knn_idx[b3 + 1];
    const int j2 = g_knn_idx[b3 + 2];
    const float w0 = g_knn_w[b3 + 0];
    const float w1 = g_knn_w[b3 + 1];
    const float w2 = g_knn_w[b3 + 2];
    const float* f0 = &g_f2[(size_t)j0 * COUT];
    const float* f1 = &g_f2[(size_t)j1 * COUT];
    const float* f2v = &g_f2[(size_t)j2 * COUT];
    float* orow = out + (size_t)warp * COUT;
    #pragma unroll
    for (int i = 0; i < 2; ++i) {
        const int c = lane * 4 + i * 128;
        const float4 a = *reinterpret_cast<const float4*>(&f0[c]);
        const float4 b = *reinterpret_cast<const float4*>(&f1[c]);
        const float4 d = *reinterpret_cast<const float4*>(&f2v[c]);
        float4 o = *reinterpret_cast<float4*>(&orow[c]);
        o.x += w0 * a.x + w1 * b.x + w2 * d.x;
        o.y += w0 * a.y + w1 * b.y + w2 * d.y;
        o.z += w0 * a.z + w1 * b.z + w2 * d.z;
        o.w += w0 * a.w + w1 * b.w + w2 * d.w;
        *reinterpret_cast<float4*>(&orow[c]) = o;
    }
}

// ---------------------------------------------------------------------------
// mma.sync split-bf16 GEMM + BN + ReLU.
//   D = Ah*Bh^T + Ah*Bl^T + Al*Bh^T  (fp32 accum in HMMA)
// CTA tile 128x128, BK=32 bf16, 8 warps (warp tile 32x64).
// 3-stage cp.async ring, ONE __syncthreads per chunk.
// ---------------------------------------------------------------------------
#define TILE_B   8192          // one 128x32-bf16 tile (128 rows x 64 B)
#define BUF_B    (4 * TILE_B)  // Ah, Al, Bh, Bl
#define NSTAGE   3
#define SM_COEFF (NSTAGE * BUF_B)
#define SM_TOT   (SM_COEFF + 1024)

template <int KD>
__global__ void __launch_bounds__(256)
mma_gemm_kernel(const __nv_bfloat16* __restrict__ Ahi,
                const __nv_bfloat16* __restrict__ Alo,
                const __nv_bfloat16* __restrict__ Bhi,
                const __nv_bfloat16* __restrict__ Blo,
                const float* __restrict__ bb, const float* __restrict__ gg,
                const float* __restrict__ be, const float* __restrict__ mm,
                const float* __restrict__ vv,
                float* __restrict__ out) {
    extern __shared__ char smem[];
    const uint32_t sbase = smem_u32(smem);
    const int tid = threadIdx.x;
    const int lane = tid & 31;
    const int wid = tid >> 5;
    const int m0 = blockIdx.x * 128;
    const int c0 = blockIdx.y * 128;

    // BN coefficients for this CTA's 128 output columns
    float* sc_s = reinterpret_cast<float*>(smem + SM_COEFF);
    float* sh_s = sc_s + 128;
    if (tid < 128) {
        const int c = c0 + tid;
        const float s = gg[c] * rsqrtf(vv[c] + BN_EPS);
        sc_s[tid] = s;
        sh_s[tid] = (bb[c] - mm[c]) * s + be[c];
    }

    const __nv_bfloat16* srcs[4] = {Ahi, Alo, Bhi, Blo};
    const int r0s[4] = {m0, m0, c0, c0};

    auto load_chunk = [&](int chunk, int stage) {
        const int k0 = chunk * 32;
        #pragma unroll
        for (int t = 0; t < 4; ++t) {
            const uint32_t tb = sbase + stage * BUF_B + t * TILE_B;
            #pragma unroll
            for (int i = 0; i < 2; ++i) {
                const int u = tid + i * 256;          // 512 16B units per tile
                const int row = u >> 2;
                const int cu = u & 3;
                cp16(tb + sw64((uint32_t)(row * 64 + cu * 16)),
                     srcs[t] + (size_t)(r0s[t] + row) * KD + k0 + cu * 8);
            }
        }
    };

    float acc[2][8][4];
    #pragma unroll
    for (int a = 0; a < 2; ++a)
        #pragma unroll
        for (int b = 0; b < 8; ++b)
            #pragma unroll
            for (int c = 0; c < 4; ++c) acc[a][b][c] = 0.f;

    const int mw = (wid & 3) * 32;   // warp M offset within CTA tile
    const int nw = (wid >> 2) * 64;  // warp N offset within CTA tile
    const int lr = lane & 15;        // ldmatrix row
    const int lc = (lane >> 4) & 1;  // ldmatrix 16B col half

    constexpr int NCH = KD / 32;
    load_chunk(0, 0); cp_commit();
    load_chunk(1, 1); cp_commit();

    for (int ch = 0; ch < NCH; ++ch) {
        cp_wait<1>();          // group `ch` (and older) complete for THIS thread
        __syncthreads();       // ... and for every thread in the CTA
        const uint32_t bufb = sbase + (ch % NSTAGE) * BUF_B;

        #pragma unroll
        for (int k16 = 0; k16 < 2; ++k16) {
            uint32_t ah[2][4], al[2][4];
            #pragma unroll
            for (int tm = 0; tm < 2; ++tm) {
                const uint32_t sw = sw64(
                    (uint32_t)((mw + tm * 16 + lr) * 64 + k16 * 32 + lc * 16));
                ldsm4(ah[tm], bufb + 0 * TILE_B + sw);
                ldsm4(al[tm], bufb + 1 * TILE_B + sw);
            }
            uint32_t bh[4][4], bl[4][4];
            #pragma unroll
            for (int t16 = 0; t16 < 4; ++t16) {
                const uint32_t sw = sw64(
                    (uint32_t)((nw + t16 * 16 + lr) * 64 + k16 * 32 + lc * 16));
                ldsm4(bh[t16], bufb + 2 * TILE_B + sw);
                ldsm4(bl[t16], bufb + 3 * TILE_B + sw);
            }
            #pragma unroll
            for (int tm = 0; tm < 2; ++tm)
                #pragma unroll
                for (int tn = 0; tn < 8; ++tn) {
                    const int t16 = tn >> 1, o = tn & 1;
                    mma16816(acc[tm][tn], ah[tm], bh[t16][o], bh[t16][o + 2]);
                    mma16816(acc[tm][tn], ah[tm], bl[t16][o], bl[t16][o + 2]);
                    mma16816(acc[tm][tn], al[tm], bh[t16][o], bh[t16][o + 2]);
                }
        }

        // Issue loads for stage ch+2 (its buffer was last READ at iter ch-1;
        // the sync above guarantees all warps are past that read).
        if (ch + 2 < NCH) load_chunk(ch + 2, (ch + 2) % NSTAGE);
        cp_commit();           // empty groups at the tail keep counts uniform
    }

    // Epilogue: BN + ReLU. acc[tm][tn][h*2+e] = row m0+mw+tm*16+h*8+g,
    //                                           col c0+nw+tn*8+2*tig+e
    const int g = lane >> 2, tig = lane & 3;
    #pragma unroll
    for (int tm = 0; tm < 2; ++tm) {
        #pragma unroll
        for (int h = 0; h < 2; ++h) {
            const int r = m0 + mw + tm * 16 + h * 8 + g;
            #pragma unroll
            for (int tn = 0; tn < 8; ++tn) {
                const int cl = nw + tn * 8 + 2 * tig;   // local col in [0,128)
                const int gc = c0 + cl;
                float o0 = fmaxf(fmaf(acc[tm][tn][h * 2 + 0], sc_s[cl + 0], sh_s[cl + 0]), 0.f);
                float o1 = fmaxf(fmaf(acc[tm][tn][h * 2 + 1], sc_s[cl + 1], sh_s[cl + 1]), 0.f);
                *reinterpret_cast<float2*>(&out[(size_t)r * COUT + gc]) =
                    make_float2(o0, o1);
            }
        }
    }
}

// ---------------------------------------------------------------------------
// Fork-join stream/event set, created ONCE at static-init time. If anything
// fails, ok stays false and kernel_launch uses the serial path.
// ---------------------------------------------------------------------------
namespace {
struct HxStreams {
    cudaStream_t s1 = nullptr, s2 = nullptr;
    cudaEvent_t eF = nullptr, e1 = nullptr, e2 = nullptr;
    bool ok = false;
    HxStreams() {
        ok = (cudaStreamCreateWithFlags(&s1, cudaStreamNonBlocking) == cudaSuccess) &&
             (cudaStreamCreateWithFlags(&s2, cudaStreamNonBlocking) == cudaSuccess) &&
             (cudaEventCreateWithFlags(&eF, cudaEventDisableTiming) == cudaSuccess) &&
             (cudaEventCreateWithFlags(&e1, cudaEventDisableTiming) == cudaSuccess) &&
             (cudaEventCreateWithFlags(&e2, cudaEventDisableTiming) == cudaSuccess);
    }
};
HxStreams g_hx;
}  // namespace

// ---------------------------------------------------------------------------
extern "C" void kernel_launch(void* const* d_in, const int* in_sizes, int n_in,
                              void* d_out, int out_size) {
    const float* points_1 = (const float*)d_in[0];
    const float* feat_1   = (const float*)d_in[1];
    const int*   rs1      = (const int*)  d_in[2];
    const float* points_2 = (const float*)d_in[3];
    const float* feat_2   = (const float*)d_in[4];
    const int*   rs2      = (const int*)  d_in[5];
    const float* w1  = (const float*)d_in[6];
    const float* b1  = (const float*)d_in[7];
    const float* g1  = (const float*)d_in[8];
    const float* be1 = (const float*)d_in[9];
    const float* m1  = (const float*)d_in[10];
    const float* v1  = (const float*)d_in[11];
    const float* w2  = (const float*)d_in[12];
    const float* b2  = (const float*)d_in[13];
    const float* g2  = (const float*)d_in[14];
    const float* be2 = (const float*)d_in[15];
    const float* m2  = (const float*)d_in[16];
    const float* v2  = (const float*)d_in[17];
    float* out = (float*)d_out;

    float* f2_ptr;        cudaGetSymbolAddress((void**)&f2_ptr, g_f2);
    __nv_bfloat16 *x1hi, *x1lo, *x2hi, *x2lo, *w1hi, *w1lo, *w2hi, *w2lo;
    cudaGetSymbolAddress((void**)&x1hi, g_x1hi);
    cudaGetSymbolAddress((void**)&x1lo, g_x1lo);
    cudaGetSymbolAddress((void**)&x2hi, g_x2hi);
    cudaGetSymbolAddress((void**)&x2lo, g_x2lo);
    cudaGetSymbolAddress((void**)&w1hi, g_w1hi);
    cudaGetSymbolAddress((void**)&w1lo, g_w1lo);
    cudaGetSymbolAddress((void**)&w2hi, g_w2hi);
    cudaGetSymbolAddress((void**)&w2lo, g_w2lo);

    cudaFuncSetAttribute(mma_gemm_kernel<CIN>,
                         cudaFuncAttributeMaxDynamicSharedMemorySize, SM_TOT);
    cudaFuncSetAttribute(mma_gemm_kernel<COUT>,
                         cudaFuncAttributeMaxDynamicSharedMemorySize, SM_TOT);

    const int n4_x2 = (N2T * CIN) / 4;
    const int n4_w2 = (COUT * CIN) / 4;
    const int n4_x1 = (N1T * COUT) / 4;
    const int n4_w1 = (COUT * COUT) / 4;
    const dim3 gg2(N2T / 128, COUT / 128);
    const dim3 ggk(64, 4);
    const dim3 gg1(N1T / 128, COUT / 128);
    const int gia = (N1T * 32) / 256;      // interp_add: 1 warp per row

    if (g_hx.ok) {
        // Fork: s1 = KNN; s2 = GEMM2 chain; s0 = GEMM1 chain (no interp).
        // Join on s0 before interp_add.
        cudaEventRecord(g_hx.eF, 0);
        cudaStreamWaitEvent(g_hx.s1, g_hx.eF, 0);
        cudaStreamWaitEvent(g_hx.s2, g_hx.eF, 0);

        // s1: KNN (independent of all GEMM work)
        knn_kernel<<<ggk, 256, 0, g_hx.s1>>>(points_1, rs1, points_2, rs2);
        cudaEventRecord(g_hx.e1, g_hx.s1);

        // s2: GEMM2 chain -> g_f2
        split_bf16_kernel<<<(n4_x2 + 255) / 256, 256, 0, g_hx.s2>>>(
            feat_2, x2hi, x2lo, n4_x2);
        split_bf16_kernel<<<(n4_w2 + 255) / 256, 256, 0, g_hx.s2>>>(
            w2, w2hi, w2lo, n4_w2);
        mma_gemm_kernel<CIN><<<gg2, 256, SM_TOT, g_hx.s2>>>(
            x2hi, x2lo, w2hi, w2lo, b2, g2, be2, m2, v2, f2_ptr);
        cudaEventRecord(g_hx.e2, g_hx.s2);

        // s0: GEMM1 chain -> out (pure linear1+BN+ReLU part)
        split_bf16_kernel<<<(n4_x1 + 255) / 256, 256>>>(feat_1, x1hi, x1lo, n4_x1);
        split_bf16_kernel<<<(n4_w1 + 255) / 256, 256>>>(w1, w1hi, w1lo, n4_w1);
        mma_gemm_kernel<COUT><<<gg1, 256, SM_TOT>>>(
            x1hi, x1lo, w1hi, w1lo, b1, g1, be1, m1, v1, out);

        // Join, then out += interp
        cudaStreamWaitEvent(0, g_hx.e1, 0);
        cudaStreamWaitEvent(0, g_hx.e2, 0);
        interp_add_kernel<<<gia, 256>>>(out);
    } else {
        // Serial fallback
        split_bf16_kernel<<<(n4_x2 + 255) / 256, 256>>>(feat_2, x2hi, x2lo, n4_x2);
        split_bf16_kernel<<<(n4_w2 + 255) / 256, 256>>>(w2, w2hi, w2lo, n4_w2);
        split_bf16_kernel<<<(n4_x1 + 255) / 256, 256>>>(feat_1, x1hi, x1lo, n4_x1);
        split_bf16_kernel<<<(n4_w1 + 255) / 256, 256>>>(w1, w1hi, w1lo, n4_w1);
        mma_gemm_kernel<CIN><<<gg2, 256, SM_TOT>>>(
            x2hi, x2lo, w2hi, w2lo, b2, g2, be2, m2, v2, f2_ptr);
        knn_kernel<<<ggk, 256>>>(points_1, rs1, points_2, rs2);
        mma_gemm_kernel<COUT><<<gg1, 256, SM_TOT>>>(
            x1hi, x1lo, w1hi, w1lo, b1, g1, be1, m1, v1, out);
        interp_add_kernel<<<gia, 256>>>(out);
    }
}

// round 14
// speedup vs baseline: 1.3696x; 1.3696x over previous
#include <cuda_runtime.h>
#include <cuda_bf16.h>
#include <math_constants.h>
#include <cstdint>

// Problem constants (fixed by setup_inputs)
#define N1T   65536
#define N2T   16384
#define CIN   512
#define COUT  256
#define BN_EPS 1e-5f

// ---------------- scratch (device globals; no allocs allowed) --------------
__device__ float g_f2[N2T * COUT];            // linear2 output, fp32 (16 MB)
__device__ int   g_knn_idx[N1T * 3];
__device__ float g_knn_w[N1T * 3];
__device__ __nv_bfloat16 g_x1hi[N1T * COUT];  // feat_1 split
__device__ __nv_bfloat16 g_x1lo[N1T * COUT];
__device__ __nv_bfloat16 g_x2hi[N2T * CIN];   // feat_2 split
__device__ __nv_bfloat16 g_x2lo[N2T * CIN];
__device__ __nv_bfloat16 g_w1hi[COUT * COUT];
__device__ __nv_bfloat16 g_w1lo[COUT * COUT];
__device__ __nv_bfloat16 g_w2hi[COUT * CIN];
__device__ __nv_bfloat16 g_w2lo[COUT * CIN];

// ---------------- PTX helpers (baseline ISA only; NO tcgen05) --------------
__device__ __forceinline__ uint32_t smem_u32(const void* p) {
    uint32_t a;
    asm("{ .reg .u64 t; cvta.to.shared.u64 t, %1; cvt.u32.u64 %0, t; }"
        : "=r"(a) : "l"(p));
    return a;
}
__device__ __forceinline__ void cp16(uint32_t saddr, const void* g) {
    asm volatile("cp.async.cg.shared.global [%0], [%1], 16;"
                 :: "r"(saddr), "l"(g) : "memory");
}
__device__ __forceinline__ void cp_commit() {
    asm volatile("cp.async.commit_group;" ::: "memory");
}
template <int N>
__device__ __forceinline__ void cp_wait() {
    asm volatile("cp.async.wait_group %0;" :: "n"(N) : "memory");
}
__device__ __forceinline__ void ldsm4(uint32_t (&r)[4], uint32_t addr) {
    asm volatile("ldmatrix.sync.aligned.m8n8.x4.shared.b16 {%0,%1,%2,%3}, [%4];"
                 : "=r"(r[0]), "=r"(r[1]), "=r"(r[2]), "=r"(r[3]) : "r"(addr));
}
__device__ __forceinline__ void mma16816(float (&d)[4], const uint32_t (&a)[4],
                                         uint32_t b0, uint32_t b1) {
    asm volatile(
        "mma.sync.aligned.m16n8k16.row.col.f32.bf16.bf16.f32 "
        "{%0,%1,%2,%3}, {%4,%5,%6,%7}, {%8,%9}, {%0,%1,%2,%3};"
        : "+f"(d[0]), "+f"(d[1]), "+f"(d[2]), "+f"(d[3])
        : "r"(a[0]), "r"(a[1]), "r"(a[2]), "r"(a[3]), "r"(b0), "r"(b1));
}
// 64B-row XOR swizzle: conflict-free ldmatrix with 64B row stride
__device__ __forceinline__ uint32_t sw64(uint32_t off) {
    return off ^ ((off >> 3) & 0x30);
}

// ---------------------------------------------------------------------------
// Split fp32 -> (hi, lo) bf16 pair
// ---------------------------------------------------------------------------
__global__ void split_bf16_kernel(const float* __restrict__ in,
                                  __nv_bfloat16* __restrict__ hi,
                                  __nv_bfloat16* __restrict__ lo, int n4) {
    int i = blockIdx.x * blockDim.x + threadIdx.x;
    if (i >= n4) return;
    float4 v = reinterpret_cast<const float4*>(in)[i];
    float vv[4] = {v.x, v.y, v.z, v.w};
    ushort4 h, l;
    unsigned short* hp = &h.x;
    unsigned short* lp = &l.x;
    #pragma unroll
    for (int j = 0; j < 4; ++j) {
        __nv_bfloat16 hb = __float2bfloat16(vv[j]);
        __nv_bfloat16 lb = __float2bfloat16(vv[j] - __bfloat162float(hb));
        hp[j] = __bfloat16_as_ushort(hb);
        lp[j] = __bfloat16_as_ushort(lb);
    }
    reinterpret_cast<ushort4*>(hi)[i] = h;
    reinterpret_cast<ushort4*>(lo)[i] = l;
}

// ---------------------------------------------------------------------------
// KNN: bit-exact d2 arithmetic (load-bearing for rel_err — do not change):
//   qq = (qx*qx + qy*qy) + qz*qz ; pp likewise
//   dot = fma(qz,pz, fma(qy,py, qx*px)) ; d2 = (qq+pp) - 2*dot
// Strict-< insertion keeps lower index on ties (matches jax.lax.top_k).
// Grid: (64, 4) — one thread per query of its segment.
// ---------------------------------------------------------------------------
#define KNN_CHUNK 2048

struct Top3 {
    float d0, d1, d2;
    int i0, i1, i2;
};

__device__ __forceinline__ void knn_point(Top3& t3, const float4 p, int gj,
                                          float qx, float qy, float qz, float qq) {
    const float dot = fmaf(qz, p.z, fmaf(qy, p.y, __fmul_rn(qx, p.x)));
    const float t = __fsub_rn(__fadd_rn(qq, p.w), __fmul_rn(2.0f, dot));
    if (t < t3.d2) {
        if (t < t3.d1) {
            t3.d2 = t3.d1; t3.i2 = t3.i1;
            if (t < t3.d0) { t3.d1 = t3.d0; t3.i1 = t3.i0; t3.d0 = t; t3.i0 = gj; }
            else           { t3.d1 = t; t3.i1 = gj; }
        } else { t3.d2 = t; t3.i2 = gj; }
    }
}

__global__ void knn_kernel(const float* __restrict__ pts1,
                           const int*   __restrict__ rs1,
                           const float* __restrict__ pts2,
                           const int*   __restrict__ rs2) {
    __shared__ float4 sp[KNN_CHUNK];

    const int seg = blockIdx.y;
    const int tid = threadIdx.x;
    const int q_start = rs1[seg], q_end = rs1[seg + 1];
    const int p_start = rs2[seg], p_end = rs2[seg + 1];
    const int nq = q_end - q_start;
    const int np = p_end - p_start;

    const int ql = blockIdx.x * blockDim.x + tid;
    const bool active = ql < nq;
    const int q = q_start + (active ? ql : 0);

    const float qx = pts1[q * 3 + 0];
    const float qy = pts1[q * 3 + 1];
    const float qz = pts1[q * 3 + 2];
    const float qq = __fadd_rn(__fadd_rn(__fmul_rn(qx, qx), __fmul_rn(qy, qy)),
                               __fmul_rn(qz, qz));

    Top3 t3 = {CUDART_INF_F, CUDART_INF_F, CUDART_INF_F, 0, 0, 0};

    for (int cb = 0; cb < np; cb += KNN_CHUNK) {
        const int cnt = min(KNN_CHUNK, np - cb);
        __syncthreads();
        for (int j = tid; j < cnt; j += blockDim.x) {
            const int pi = p_start + cb + j;
            const float px = pts2[pi * 3 + 0];
            const float py = pts2[pi * 3 + 1];
            const float pz = pts2[pi * 3 + 2];
            const float pp = __fadd_rn(
                __fadd_rn(__fmul_rn(px, px), __fmul_rn(py, py)),
                __fmul_rn(pz, pz));
            sp[j] = make_float4(px, py, pz, pp);
        }
        __syncthreads();
        if (active) {
            if (cnt == KNN_CHUNK) {        // fast path: static trip count
                #pragma unroll 8
                for (int j = 0; j < KNN_CHUNK; ++j)
                    knn_point(t3, sp[j], cb + j, qx, qy, qz, qq);
            } else {
                for (int j = 0; j < cnt; ++j)
                    knn_point(t3, sp[j], cb + j, qx, qy, qz, qq);
            }
        }
    }

    if (active) {
        const float e0 = fmaxf(t3.d0, 0.f), e1 = fmaxf(t3.d1, 0.f), e2 = fmaxf(t3.d2, 0.f);
        const float w0 = 1.f / (e0 + 1e-8f);
        const float w1 = 1.f / (e1 + 1e-8f);
        const float w2 = 1.f / (e2 + 1e-8f);
        const float inv = 1.f / (w0 + w1 + w2);
        const int base = q * 3;
        g_knn_idx[base + 0] = p_start + t3.i0;  g_knn_w[base + 0] = w0 * inv;
        g_knn_idx[base + 1] = p_start + t3.i1;  g_knn_w[base + 1] = w1 * inv;
        g_knn_idx[base + 2] = p_start + t3.i2;  g_knn_w[base + 2] = w2 * inv;
    }
}

// ---------------------------------------------------------------------------
// mma.sync split-bf16 GEMM + BN + ReLU (+ fused interp gather).
//   D = Ah*Bh^T + Ah*Bl^T + Al*Bh^T  (fp32 accum in HMMA)
// CTA tile 128x128, BK=32 bf16, 8 warps (warp tile 32x64).
// 3-stage cp.async ring, ONE __syncthreads per chunk.
// __launch_bounds__(256, 2): 2 CTAs/SM (2x97KB smem = 194KB <= 228KB,
// 2x256x127 regs = 65024 <= 64K+512) — cross-CTA overlap hides sync/LDSM
// bubbles that capped tensor pipe at 47% with 1 CTA/SM.
// ---------------------------------------------------------------------------
#define TILE_B   8192          // one 128x32-bf16 tile (128 rows x 64 B)
#define BUF_B    (4 * TILE_B)  // Ah, Al, Bh, Bl
#define NSTAGE   3
#define SM_COEFF (NSTAGE * BUF_B)
#define SM_TOT   (SM_COEFF + 1024)

template <int KD, bool INTERP>
__global__ void __launch_bounds__(256, 2)
mma_gemm_kernel(const __nv_bfloat16* __restrict__ Ahi,
                const __nv_bfloat16* __restrict__ Alo,
                const __nv_bfloat16* __restrict__ Bhi,
                const __nv_bfloat16* __restrict__ Blo,
                const float* __restrict__ bb, const float* __restrict__ gg,
                const float* __restrict__ be, const float* __restrict__ mm,
                const float* __restrict__ vv,
                float* __restrict__ out) {
    extern __shared__ char smem[];
    const uint32_t sbase = smem_u32(smem);
    const int tid = threadIdx.x;
    const int lane = tid & 31;
    const int wid = tid >> 5;
    const int m0 = blockIdx.x * 128;
    const int c0 = blockIdx.y * 128;

    // BN coefficients for this CTA's 128 output columns
    float* sc_s = reinterpret_cast<float*>(smem + SM_COEFF);
    float* sh_s = sc_s + 128;
    if (tid < 128) {
        const int c = c0 + tid;
        const float s = gg[c] * rsqrtf(vv[c] + BN_EPS);
        sc_s[tid] = s;
        sh_s[tid] = (bb[c] - mm[c]) * s + be[c];
    }

    const __nv_bfloat16* srcs[4] = {Ahi, Alo, Bhi, Blo};
    const int r0s[4] = {m0, m0, c0, c0};

    auto load_chunk = [&](int chunk, int stage) {
        const int k0 = chunk * 32;
        #pragma unroll
        for (int t = 0; t < 4; ++t) {
            const uint32_t tb = sbase + stage * BUF_B + t * TILE_B;
            #pragma unroll
            for (int i = 0; i < 2; ++i) {
                const int u = tid + i * 256;          // 512 16B units per tile
                const int row = u >> 2;
                const int cu = u & 3;
                cp16(tb + sw64((uint32_t)(row * 64 + cu * 16)),
                     srcs[t] + (size_t)(r0s[t] + row) * KD + k0 + cu * 8);
            }
        }
    };

    float acc[2][8][4];
    #pragma unroll
    for (int a = 0; a < 2; ++a)
        #pragma unroll
        for (int b = 0; b < 8; ++b)
            #pragma unroll
            for (int c = 0; c < 4; ++c) acc[a][b][c] = 0.f;

    const int mw = (wid & 3) * 32;   // warp M offset within CTA tile
    const int nw = (wid >> 2) * 64;  // warp N offset within CTA tile
    const int lr = lane & 15;        // ldmatrix row
    const int lc = (lane >> 4) & 1;  // ldmatrix 16B col half

    constexpr int NCH = KD / 32;
    load_chunk(0, 0); cp_commit();
    load_chunk(1, 1); cp_commit();

    for (int ch = 0; ch < NCH; ++ch) {
        cp_wait<1>();          // group `ch` (and older) complete for THIS thread
        __syncthreads();       // ... and for every thread in the CTA
        const uint32_t bufb = sbase + (ch % NSTAGE) * BUF_B;

        #pragma unroll
        for (int k16 = 0; k16 < 2; ++k16) {
            uint32_t ah[2][4], al[2][4];
            #pragma unroll
            for (int tm = 0; tm < 2; ++tm) {
                const uint32_t sw = sw64(
                    (uint32_t)((mw + tm * 16 + lr) * 64 + k16 * 32 + lc * 16));
                ldsm4(ah[tm], bufb + 0 * TILE_B + sw);
                ldsm4(al[tm], bufb + 1 * TILE_B + sw);
            }
            uint32_t bh[4][4], bl[4][4];
            #pragma unroll
            for (int t16 = 0; t16 < 4; ++t16) {
                const uint32_t sw = sw64(
                    (uint32_t)((nw + t16 * 16 + lr) * 64 + k16 * 32 + lc * 16));
                ldsm4(bh[t16], bufb + 2 * TILE_B + sw);
                ldsm4(bl[t16], bufb + 3 * TILE_B + sw);
            }
            #pragma unroll
            for (int tm = 0; tm < 2; ++tm)
                #pragma unroll
                for (int tn = 0; tn < 8; ++tn) {
                    const int t16 = tn >> 1, o = tn & 1;
                    mma16816(acc[tm][tn], ah[tm], bh[t16][o], bh[t16][o + 2]);
                    mma16816(acc[tm][tn], ah[tm], bl[t16][o], bl[t16][o + 2]);
                    mma16816(acc[tm][tn], al[tm], bh[t16][o], bh[t16][o + 2]);
                }
        }

        // Issue loads for stage ch+2 (its buffer was last READ at iter ch-1;
        // the sync above guarantees all warps are past that read).
        if (ch + 2 < NCH) load_chunk(ch + 2, (ch + 2) % NSTAGE);
        cp_commit();           // empty groups at the tail keep counts uniform
    }

    // Epilogue. acc[tm][tn][h*2+e] = row m0+mw+tm*16+h*8+g,
    //                                col c0+nw+tn*8+2*tig+e
    const int g = lane >> 2, tig = lane & 3;

    // Batch the first-hop gather loads (idx+weights) for all 4 row contexts.
    int jj[2][2][3];
    float ww[2][2][3];
    if (INTERP) {
        #pragma unroll
        for (int tm = 0; tm < 2; ++tm)
            #pragma unroll
            for (int h = 0; h < 2; ++h) {
                const int r = m0 + mw + tm * 16 + h * 8 + g;
                const int b3 = r * 3;
                jj[tm][h][0] = g_knn_idx[b3 + 0];
                jj[tm][h][1] = g_knn_idx[b3 + 1];
                jj[tm][h][2] = g_knn_idx[b3 + 2];
                ww[tm][h][0] = g_knn_w[b3 + 0];
                ww[tm][h][1] = g_knn_w[b3 + 1];
                ww[tm][h][2] = g_knn_w[b3 + 2];
            }
    }

    #pragma unroll
    for (int tm = 0; tm < 2; ++tm) {
        #pragma unroll
        for (int h = 0; h < 2; ++h) {
            const int r = m0 + mw + tm * 16 + h * 8 + g;
            #pragma unroll
            for (int tn = 0; tn < 8; ++tn) {
                const int cl = nw + tn * 8 + 2 * tig;   // local col in [0,128)
                const int gc = c0 + cl;
                float o0 = fmaxf(fmaf(acc[tm][tn][h * 2 + 0], sc_s[cl + 0], sh_s[cl + 0]), 0.f);
                float o1 = fmaxf(fmaf(acc[tm][tn][h * 2 + 1], sc_s[cl + 1], sh_s[cl + 1]), 0.f);
                if (INTERP) {
                    const float2 f0 = *reinterpret_cast<const float2*>(
                        &g_f2[(size_t)jj[tm][h][0] * COUT + gc]);
                    const float2 f1 = *reinterpret_cast<const float2*>(
                        &g_f2[(size_t)jj[tm][h][1] * COUT + gc]);
                    const float2 f2v = *reinterpret_cast<const float2*>(
                        &g_f2[(size_t)jj[tm][h][2] * COUT + gc]);
                    o0 += ww[tm][h][0] * f0.x + ww[tm][h][1] * f1.x + ww[tm][h][2] * f2v.x;
                    o1 += ww[tm][h][0] * f0.y + ww[tm][h][1] * f1.y + ww[tm][h][2] * f2v.y;
                }
                *reinterpret_cast<float2*>(&out[(size_t)r * COUT + gc]) =
                    make_float2(o0, o1);
            }
        }
    }
}

// ---------------------------------------------------------------------------
// Fork-join stream/event set, created ONCE at static-init time. If anything
// fails, ok stays false and kernel_launch uses the serial path.
// ---------------------------------------------------------------------------
namespace {
struct HxStreams {
    cudaStream_t s1 = nullptr, s2 = nullptr;
    cudaEvent_t eF = nullptr, e1 = nullptr, e2 = nullptr;
    bool ok = false;
    HxStreams() {
        ok = (cudaStreamCreateWithFlags(&s1, cudaStreamNonBlocking) == cudaSuccess) &&
             (cudaStreamCreateWithFlags(&s2, cudaStreamNonBlocking) == cudaSuccess) &&
             (cudaEventCreateWithFlags(&eF, cudaEventDisableTiming) == cudaSuccess) &&
             (cudaEventCreateWithFlags(&e1, cudaEventDisableTiming) == cudaSuccess) &&
             (cudaEventCreateWithFlags(&e2, cudaEventDisableTiming) == cudaSuccess);
    }
};
HxStreams g_hx;
}  // namespace

// ---------------------------------------------------------------------------
extern "C" void kernel_launch(void* const* d_in, const int* in_sizes, int n_in,
                              void* d_out, int out_size) {
    const float* points_1 = (const float*)d_in[0];
    const float* feat_1   = (const float*)d_in[1];
    const int*   rs1      = (const int*)  d_in[2];
    const float* points_2 = (const float*)d_in[3];
    const float* feat_2   = (const float*)d_in[4];
    const int*   rs2      = (const int*)  d_in[5];
    const float* w1  = (const float*)d_in[6];
    const float* b1  = (const float*)d_in[7];
    const float* g1  = (const float*)d_in[8];
    const float* be1 = (const float*)d_in[9];
    const float* m1  = (const float*)d_in[10];
    const float* v1  = (const float*)d_in[11];
    const float* w2  = (const float*)d_in[12];
    const float* b2  = (const float*)d_in[13];
    const float* g2  = (const float*)d_in[14];
    const float* be2 = (const float*)d_in[15];
    const float* m2  = (const float*)d_in[16];
    const float* v2  = (const float*)d_in[17];
    float* out = (float*)d_out;

    float* f2_ptr;        cudaGetSymbolAddress((void**)&f2_ptr, g_f2);
    __nv_bfloat16 *x1hi, *x1lo, *x2hi, *x2lo, *w1hi, *w1lo, *w2hi, *w2lo;
    cudaGetSymbolAddress((void**)&x1hi, g_x1hi);
    cudaGetSymbolAddress((void**)&x1lo, g_x1lo);
    cudaGetSymbolAddress((void**)&x2hi, g_x2hi);
    cudaGetSymbolAddress((void**)&x2lo, g_x2lo);
    cudaGetSymbolAddress((void**)&w1hi, g_w1hi);
    cudaGetSymbolAddress((void**)&w1lo, g_w1lo);
    cudaGetSymbolAddress((void**)&w2hi, g_w2hi);
    cudaGetSymbolAddress((void**)&w2lo, g_w2lo);

    cudaFuncSetAttribute(mma_gemm_kernel<CIN, false>,
                         cudaFuncAttributeMaxDynamicSharedMemorySize, SM_TOT);
    cudaFuncSetAttribute(mma_gemm_kernel<COUT, true>,
                         cudaFuncAttributeMaxDynamicSharedMemorySize, SM_TOT);

    const int n4_x2 = (N2T * CIN) / 4;
    const int n4_w2 = (COUT * CIN) / 4;
    const int n4_x1 = (N1T * COUT) / 4;
    const int n4_w1 = (COUT * COUT) / 4;
    const dim3 gg2(N2T / 128, COUT / 128);
    const dim3 ggk(64, 4);
    const dim3 gg1(N1T / 128, COUT / 128);

    if (g_hx.ok) {
        // Fork: s1 runs KNN; s2 runs the GEMM1-only splits; stream 0 runs
        // the GEMM2 chain. Join before the fused GEMM1.
        cudaEventRecord(g_hx.eF, 0);
        cudaStreamWaitEvent(g_hx.s1, g_hx.eF, 0);
        cudaStreamWaitEvent(g_hx.s2, g_hx.eF, 0);

        // s1: KNN (independent of all GEMM work)
        knn_kernel<<<ggk, 256, 0, g_hx.s1>>>(points_1, rs1, points_2, rs2);
        cudaEventRecord(g_hx.e1, g_hx.s1);

        // s2: splits needed only by GEMM1
        split_bf16_kernel<<<(n4_x1 + 255) / 256, 256, 0, g_hx.s2>>>(
            feat_1, x1hi, x1lo, n4_x1);
        split_bf16_kernel<<<(n4_w1 + 255) / 256, 256, 0, g_hx.s2>>>(
            w1, w1hi, w1lo, n4_w1);
        cudaEventRecord(g_hx.e2, g_hx.s2);

        // stream 0: splits for GEMM2, then GEMM2
        split_bf16_kernel<<<(n4_x2 + 255) / 256, 256>>>(feat_2, x2hi, x2lo, n4_x2);
        split_bf16_kernel<<<(n4_w2 + 255) / 256, 256>>>(w2, w2hi, w2lo, n4_w2);
        mma_gemm_kernel<CIN, false><<<gg2, 256, SM_TOT>>>(
            x2hi, x2lo, w2hi, w2lo, b2, g2, be2, m2, v2, f2_ptr);

        // Join, then fused GEMM1 (+interp) on stream 0
        cudaStreamWaitEvent(0, g_hx.e1, 0);
        cudaStreamWaitEvent(0, g_hx.e2, 0);
        mma_gemm_kernel<COUT, true><<<gg1, 256, SM_TOT>>>(
            x1hi, x1lo, w1hi, w1lo, b1, g1, be1, m1, v1, out);
    } else {
        // Serial fallback
        split_bf16_kernel<<<(n4_x2 + 255) / 256, 256>>>(feat_2, x2hi, x2lo, n4_x2);
        split_bf16_kernel<<<(n4_w2 + 255) / 256, 256>>>(w2, w2hi, w2lo, n4_w2);
        split_bf16_kernel<<<(n4_x1 + 255) / 256, 256>>>(feat_1, x1hi, x1lo, n4_x1);
        split_bf16_kernel<<<(n4_w1 + 255) / 256, 256>>>(w1, w1hi, w1lo, n4_w1);
        mma_gemm_kernel<CIN, false><<<gg2, 256, SM_TOT>>>(
            x2hi, x2lo, w2hi, w2lo, b2, g2, be2, m2, v2, f2_ptr);
        knn_kernel<<<ggk, 256>>>(points_1, rs1, points_2, rs2);
        mma_gemm_kernel<COUT, true><<<gg1, 256, SM_TOT>>>(
            x1hi, x1lo, w1hi, w1lo, b1, g1, be1, m1, v1, out);
    }
}

// round 15
// speedup vs baseline: 1.5463x; 1.1290x over previous
#include <cuda_runtime.h>
#include <cuda_bf16.h>
#include <math_constants.h>
#include <cstdint>

// Problem constants (fixed by setup_inputs)
#define N1T   65536
#define N2T   16384
#define CIN   512
#define COUT  256
#define BN_EPS 1e-5f

// ---------------- scratch (device globals; no allocs allowed) --------------
__device__ float g_f2[N2T * COUT];            // linear2 output, fp32 (16 MB)
__device__ int   g_knn_idx[N1T * 3];
__device__ float g_knn_w[N1T * 3];
__device__ __nv_bfloat16 g_x1hi[N1T * COUT];  // feat_1 split
__device__ __nv_bfloat16 g_x1lo[N1T * COUT];
__device__ __nv_bfloat16 g_x2hi[N2T * CIN];   // feat_2 split
__device__ __nv_bfloat16 g_x2lo[N2T * CIN];
__device__ __nv_bfloat16 g_w1hi[COUT * COUT];
__device__ __nv_bfloat16 g_w1lo[COUT * COUT];
__device__ __nv_bfloat16 g_w2hi[COUT * CIN];
__device__ __nv_bfloat16 g_w2lo[COUT * CIN];

// ---------------- PTX helpers (baseline ISA only; NO tcgen05) --------------
__device__ __forceinline__ uint32_t smem_u32(const void* p) {
    uint32_t a;
    asm("{ .reg .u64 t; cvta.to.shared.u64 t, %1; cvt.u32.u64 %0, t; }"
        : "=r"(a) : "l"(p));
    return a;
}
__device__ __forceinline__ void cp16(uint32_t saddr, const void* g) {
    asm volatile("cp.async.cg.shared.global [%0], [%1], 16;"
                 :: "r"(saddr), "l"(g) : "memory");
}
__device__ __forceinline__ void cp_commit() {
    asm volatile("cp.async.commit_group;" ::: "memory");
}
template <int N>
__device__ __forceinline__ void cp_wait() {
    asm volatile("cp.async.wait_group %0;" :: "n"(N) : "memory");
}
__device__ __forceinline__ void ldsm4(uint32_t (&r)[4], uint32_t addr) {
    asm volatile("ldmatrix.sync.aligned.m8n8.x4.shared.b16 {%0,%1,%2,%3}, [%4];"
                 : "=r"(r[0]), "=r"(r[1]), "=r"(r[2]), "=r"(r[3]) : "r"(addr));
}
__device__ __forceinline__ void mma16816(float (&d)[4], const uint32_t (&a)[4],
                                         uint32_t b0, uint32_t b1) {
    asm volatile(
        "mma.sync.aligned.m16n8k16.row.col.f32.bf16.bf16.f32 "
        "{%0,%1,%2,%3}, {%4,%5,%6,%7}, {%8,%9}, {%0,%1,%2,%3};"
        : "+f"(d[0]), "+f"(d[1]), "+f"(d[2]), "+f"(d[3])
        : "r"(a[0]), "r"(a[1]), "r"(a[2]), "r"(a[3]), "r"(b0), "r"(b1));
}
// 64B-row XOR swizzle: conflict-free ldmatrix with 64B row stride
__device__ __forceinline__ uint32_t sw64(uint32_t off) {
    return off ^ ((off >> 3) & 0x30);
}

// ---------------------------------------------------------------------------
// Split fp32 -> (hi, lo) bf16 pair
// ---------------------------------------------------------------------------
__global__ void split_bf16_kernel(const float* __restrict__ in,
                                  __nv_bfloat16* __restrict__ hi,
                                  __nv_bfloat16* __restrict__ lo, int n4) {
    int i = blockIdx.x * blockDim.x + threadIdx.x;
    if (i >= n4) return;
    float4 v = reinterpret_cast<const float4*>(in)[i];
    float vv[4] = {v.x, v.y, v.z, v.w};
    ushort4 h, l;
    unsigned short* hp = &h.x;
    unsigned short* lp = &l.x;
    #pragma unroll
    for (int j = 0; j < 4; ++j) {
        __nv_bfloat16 hb = __float2bfloat16(vv[j]);
        __nv_bfloat16 lb = __float2bfloat16(vv[j] - __bfloat162float(hb));
        hp[j] = __bfloat16_as_ushort(hb);
        lp[j] = __bfloat16_as_ushort(lb);
    }
    reinterpret_cast<ushort4*>(hi)[i] = h;
    reinterpret_cast<ushort4*>(lo)[i] = l;
}

// ---------------------------------------------------------------------------
// KNN: bit-exact d2 arithmetic (load-bearing for rel_err — do not change):
//   qq = (qx*qx + qy*qy) + qz*qz ; pp likewise
//   dot = fma(qz,pz, fma(qy,py, qx*px)) ; d2 = (qq+pp) - 2*dot
// Strict-< insertion keeps lower index on ties (matches jax.lax.top_k).
// Grid: (64, 4) — one thread per query of its segment.
// ---------------------------------------------------------------------------
#define KNN_CHUNK 2048

struct Top3 {
    float d0, d1, d2;
    int i0, i1, i2;
};

__device__ __forceinline__ void knn_point(Top3& t3, const float4 p, int gj,
                                          float qx, float qy, float qz, float qq) {
    const float dot = fmaf(qz, p.z, fmaf(qy, p.y, __fmul_rn(qx, p.x)));
    const float t = __fsub_rn(__fadd_rn(qq, p.w), __fmul_rn(2.0f, dot));
    if (t < t3.d2) {
        if (t < t3.d1) {
            t3.d2 = t3.d1; t3.i2 = t3.i1;
            if (t < t3.d0) { t3.d1 = t3.d0; t3.i1 = t3.i0; t3.d0 = t; t3.i0 = gj; }
            else           { t3.d1 = t; t3.i1 = gj; }
        } else { t3.d2 = t; t3.i2 = gj; }
    }
}

__global__ void knn_kernel(const float* __restrict__ pts1,
                           const int*   __restrict__ rs1,
                           const float* __restrict__ pts2,
                           const int*   __restrict__ rs2) {
    __shared__ float4 sp[KNN_CHUNK];

    const int seg = blockIdx.y;
    const int tid = threadIdx.x;
    const int q_start = rs1[seg], q_end = rs1[seg + 1];
    const int p_start = rs2[seg], p_end = rs2[seg + 1];
    const int nq = q_end - q_start;
    const int np = p_end - p_start;

    const int ql = blockIdx.x * blockDim.x + tid;
    const bool active = ql < nq;
    const int q = q_start + (active ? ql : 0);

    const float qx = pts1[q * 3 + 0];
    const float qy = pts1[q * 3 + 1];
    const float qz = pts1[q * 3 + 2];
    const float qq = __fadd_rn(__fadd_rn(__fmul_rn(qx, qx), __fmul_rn(qy, qy)),
                               __fmul_rn(qz, qz));

    Top3 t3 = {CUDART_INF_F, CUDART_INF_F, CUDART_INF_F, 0, 0, 0};

    for (int cb = 0; cb < np; cb += KNN_CHUNK) {
        const int cnt = min(KNN_CHUNK, np - cb);
        __syncthreads();
        for (int j = tid; j < cnt; j += blockDim.x) {
            const int pi = p_start + cb + j;
            const float px = pts2[pi * 3 + 0];
            const float py = pts2[pi * 3 + 1];
            const float pz = pts2[pi * 3 + 2];
            const float pp = __fadd_rn(
                __fadd_rn(__fmul_rn(px, px), __fmul_rn(py, py)),
                __fmul_rn(pz, pz));
            sp[j] = make_float4(px, py, pz, pp);
        }
        __syncthreads();
        if (active) {
            if (cnt == KNN_CHUNK) {        // fast path: static trip count
                #pragma unroll 8
                for (int j = 0; j < KNN_CHUNK; ++j)
                    knn_point(t3, sp[j], cb + j, qx, qy, qz, qq);
            } else {
                for (int j = 0; j < cnt; ++j)
                    knn_point(t3, sp[j], cb + j, qx, qy, qz, qq);
            }
        }
    }

    if (active) {
        const float e0 = fmaxf(t3.d0, 0.f), e1 = fmaxf(t3.d1, 0.f), e2 = fmaxf(t3.d2, 0.f);
        const float w0 = 1.f / (e0 + 1e-8f);
        const float w1 = 1.f / (e1 + 1e-8f);
        const float w2 = 1.f / (e2 + 1e-8f);
        const float inv = 1.f / (w0 + w1 + w2);
        const int base = q * 3;
        g_knn_idx[base + 0] = p_start + t3.i0;  g_knn_w[base + 0] = w0 * inv;
        g_knn_idx[base + 1] = p_start + t3.i1;  g_knn_w[base + 1] = w1 * inv;
        g_knn_idx[base + 2] = p_start + t3.i2;  g_knn_w[base + 2] = w2 * inv;
    }
}

// ---------------------------------------------------------------------------
// interp_add: out[r, :] += w0*f2[j0,:] + w1*f2[j1,:] + w2*f2[j2,:]
// One warp per row; each lane covers 8 cols as 2 float4 slices.
// Same add-ordering as the previously fused epilogue -> identical rounding.
// ---------------------------------------------------------------------------
__global__ void __launch_bounds__(256)
interp_add_kernel(float* __restrict__ out) {
    const int warp = (blockIdx.x * blockDim.x + threadIdx.x) >> 5;
    const int lane = threadIdx.x & 31;
    const int b3 = warp * 3;
    const int j0 = g_knn_idx[b3 + 0];
    const int j1 = g_knn_idx[b3 + 1];
    const int j2 = g_knn_idx[b3 + 2];
    const float w0 = g_knn_w[b3 + 0];
    const float w1 = g_knn_w[b3 + 1];
    const float w2 = g_knn_w[b3 + 2];
    const float* f0 = &g_f2[(size_t)j0 * COUT];
    const float* f1 = &g_f2[(size_t)j1 * COUT];
    const float* f2v = &g_f2[(size_t)j2 * COUT];
    float* orow = out + (size_t)warp * COUT;
    #pragma unroll
    for (int i = 0; i < 2; ++i) {
        const int c = lane * 4 + i * 128;
        const float4 a = *reinterpret_cast<const float4*>(&f0[c]);
        const float4 b = *reinterpret_cast<const float4*>(&f1[c]);
        const float4 d = *reinterpret_cast<const float4*>(&f2v[c]);
        float4 o = *reinterpret_cast<float4*>(&orow[c]);
        o.x += w0 * a.x + w1 * b.x + w2 * d.x;
        o.y += w0 * a.y + w1 * b.y + w2 * d.y;
        o.z += w0 * a.z + w1 * b.z + w2 * d.z;
        o.w += w0 * a.w + w1 * b.w + w2 * d.w;
        *reinterpret_cast<float4*>(&orow[c]) = o;
    }
}

// ---------------------------------------------------------------------------
// mma.sync split-bf16 GEMM + BN + ReLU.
//   D = Ah*Bh^T + Ah*Bl^T + Al*Bh^T  (fp32 accum in HMMA)
// CTA tile 128x128, BK=32 bf16, 8 warps (warp tile 32x64).
// 3-stage cp.async ring, ONE __syncthreads per chunk.
// __launch_bounds__(256, 2): 2 CTAs/SM.
// ---------------------------------------------------------------------------
#define TILE_B   8192          // one 128x32-bf16 tile (128 rows x 64 B)
#define BUF_B    (4 * TILE_B)  // Ah, Al, Bh, Bl
#define NSTAGE   3
#define SM_COEFF (NSTAGE * BUF_B)
#define SM_TOT   (SM_COEFF + 1024)

template <int KD>
__global__ void __launch_bounds__(256, 2)
mma_gemm_kernel(const __nv_bfloat16* __restrict__ Ahi,
                const __nv_bfloat16* __restrict__ Alo,
                const __nv_bfloat16* __restrict__ Bhi,
                const __nv_bfloat16* __restrict__ Blo,
                const float* __restrict__ bb, const float* __restrict__ gg,
                const float* __restrict__ be, const float* __restrict__ mm,
                const float* __restrict__ vv,
                float* __restrict__ out) {
    extern __shared__ char smem[];
    const uint32_t sbase = smem_u32(smem);
    const int tid = threadIdx.x;
    const int lane = tid & 31;
    const int wid = tid >> 5;
    const int m0 = blockIdx.x * 128;
    const int c0 = blockIdx.y * 128;

    // BN coefficients for this CTA's 128 output columns
    float* sc_s = reinterpret_cast<float*>(smem + SM_COEFF);
    float* sh_s = sc_s + 128;
    if (tid < 128) {
        const int c = c0 + tid;
        const float s = gg[c] * rsqrtf(vv[c] + BN_EPS);
        sc_s[tid] = s;
        sh_s[tid] = (bb[c] - mm[c]) * s + be[c];
    }

    const __nv_bfloat16* srcs[4] = {Ahi, Alo, Bhi, Blo};
    const int r0s[4] = {m0, m0, c0, c0};

    auto load_chunk = [&](int chunk, int stage) {
        const int k0 = chunk * 32;
        #pragma unroll
        for (int t = 0; t < 4; ++t) {
            const uint32_t tb = sbase + stage * BUF_B + t * TILE_B;
            #pragma unroll
            for (int i = 0; i < 2; ++i) {
                const int u = tid + i * 256;          // 512 16B units per tile
                const int row = u >> 2;
                const int cu = u & 3;
                cp16(tb + sw64((uint32_t)(row * 64 + cu * 16)),
                     srcs[t] + (size_t)(r0s[t] + row) * KD + k0 + cu * 8);
            }
        }
    };

    float acc[2][8][4];
    #pragma unroll
    for (int a = 0; a < 2; ++a)
        #pragma unroll
        for (int b = 0; b < 8; ++b)
            #pragma unroll
            for (int c = 0; c < 4; ++c) acc[a][b][c] = 0.f;

    const int mw = (wid & 3) * 32;   // warp M offset within CTA tile
    const int nw = (wid >> 2) * 64;  // warp N offset within CTA tile
    const int lr = lane & 15;        // ldmatrix row
    const int lc = (lane >> 4) & 1;  // ldmatrix 16B col half

    constexpr int NCH = KD / 32;
    load_chunk(0, 0); cp_commit();
    load_chunk(1, 1); cp_commit();

    for (int ch = 0; ch < NCH; ++ch) {
        cp_wait<1>();          // group `ch` (and older) complete for THIS thread
        __syncthreads();       // ... and for every thread in the CTA
        const uint32_t bufb = sbase + (ch % NSTAGE) * BUF_B;

        #pragma unroll
        for (int k16 = 0; k16 < 2; ++k16) {
            uint32_t ah[2][4], al[2][4];
            #pragma unroll
            for (int tm = 0; tm < 2; ++tm) {
                const uint32_t sw = sw64(
                    (uint32_t)((mw + tm * 16 + lr) * 64 + k16 * 32 + lc * 16));
                ldsm4(ah[tm], bufb + 0 * TILE_B + sw);
                ldsm4(al[tm], bufb + 1 * TILE_B + sw);
            }
            uint32_t bh[4][4], bl[4][4];
            #pragma unroll
            for (int t16 = 0; t16 < 4; ++t16) {
                const uint32_t sw = sw64(
                    (uint32_t)((nw + t16 * 16 + lr) * 64 + k16 * 32 + lc * 16));
                ldsm4(bh[t16], bufb + 2 * TILE_B + sw);
                ldsm4(bl[t16], bufb + 3 * TILE_B + sw);
            }
            #pragma unroll
            for (int tm = 0; tm < 2; ++tm)
                #pragma unroll
                for (int tn = 0; tn < 8; ++tn) {
                    const int t16 = tn >> 1, o = tn & 1;
                    mma16816(acc[tm][tn], ah[tm], bh[t16][o], bh[t16][o + 2]);
                    mma16816(acc[tm][tn], ah[tm], bl[t16][o], bl[t16][o + 2]);
                    mma16816(acc[tm][tn], al[tm], bh[t16][o], bh[t16][o + 2]);
                }
        }

        // Issue loads for stage ch+2 (its buffer was last READ at iter ch-1;
        // the sync above guarantees all warps are past that read).
        if (ch + 2 < NCH) load_chunk(ch + 2, (ch + 2) % NSTAGE);
        cp_commit();           // empty groups at the tail keep counts uniform
    }

    // Epilogue: BN + ReLU. acc[tm][tn][h*2+e] = row m0+mw+tm*16+h*8+g,
    //                                           col c0+nw+tn*8+2*tig+e
    const int g = lane >> 2, tig = lane & 3;
    #pragma unroll
    for (int tm = 0; tm < 2; ++tm) {
        #pragma unroll
        for (int h = 0; h < 2; ++h) {
            const int r = m0 + mw + tm * 16 + h * 8 + g;
            #pragma unroll
            for (int tn = 0; tn < 8; ++tn) {
                const int cl = nw + tn * 8 + 2 * tig;   // local col in [0,128)
                const int gc = c0 + cl;
                float o0 = fmaxf(fmaf(acc[tm][tn][h * 2 + 0], sc_s[cl + 0], sh_s[cl + 0]), 0.f);
                float o1 = fmaxf(fmaf(acc[tm][tn][h * 2 + 1], sc_s[cl + 1], sh_s[cl + 1]), 0.f);
                *reinterpret_cast<float2*>(&out[(size_t)r * COUT + gc]) =
                    make_float2(o0, o1);
            }
        }
    }
}

// ---------------------------------------------------------------------------
// Fork-join stream/event set, created ONCE at static-init time. If anything
// fails, ok stays false and kernel_launch uses the serial path.
// ---------------------------------------------------------------------------
namespace {
struct HxStreams {
    cudaStream_t s1 = nullptr, s2 = nullptr;
    cudaEvent_t eF = nullptr, e1 = nullptr, e2 = nullptr;
    bool ok = false;
    HxStreams() {
        ok = (cudaStreamCreateWithFlags(&s1, cudaStreamNonBlocking) == cudaSuccess) &&
             (cudaStreamCreateWithFlags(&s2, cudaStreamNonBlocking) == cudaSuccess) &&
             (cudaEventCreateWithFlags(&eF, cudaEventDisableTiming) == cudaSuccess) &&
             (cudaEventCreateWithFlags(&e1, cudaEventDisableTiming) == cudaSuccess) &&
             (cudaEventCreateWithFlags(&e2, cudaEventDisableTiming) == cudaSuccess);
    }
};
HxStreams g_hx;
}  // namespace

// ---------------------------------------------------------------------------
extern "C" void kernel_launch(void* const* d_in, const int* in_sizes, int n_in,
                              void* d_out, int out_size) {
    const float* points_1 = (const float*)d_in[0];
    const float* feat_1   = (const float*)d_in[1];
    const int*   rs1      = (const int*)  d_in[2];
    const float* points_2 = (const float*)d_in[3];
    const float* feat_2   = (const float*)d_in[4];
    const int*   rs2      = (const int*)  d_in[5];
    const float* w1  = (const float*)d_in[6];
    const float* b1  = (const float*)d_in[7];
    const float* g1  = (const float*)d_in[8];
    const float* be1 = (const float*)d_in[9];
    const float* m1  = (const float*)d_in[10];
    const float* v1  = (const float*)d_in[11];
    const float* w2  = (const float*)d_in[12];
    const float* b2  = (const float*)d_in[13];
    const float* g2  = (const float*)d_in[14];
    const float* be2 = (const float*)d_in[15];
    const float* m2  = (const float*)d_in[16];
    const float* v2  = (const float*)d_in[17];
    float* out = (float*)d_out;

    float* f2_ptr;        cudaGetSymbolAddress((void**)&f2_ptr, g_f2);
    __nv_bfloat16 *x1hi, *x1lo, *x2hi, *x2lo, *w1hi, *w1lo, *w2hi, *w2lo;
    cudaGetSymbolAddress((void**)&x1hi, g_x1hi);
    cudaGetSymbolAddress((void**)&x1lo, g_x1lo);
    cudaGetSymbolAddress((void**)&x2hi, g_x2hi);
    cudaGetSymbolAddress((void**)&x2lo, g_x2lo);
    cudaGetSymbolAddress((void**)&w1hi, g_w1hi);
    cudaGetSymbolAddress((void**)&w1lo, g_w1lo);
    cudaGetSymbolAddress((void**)&w2hi, g_w2hi);
    cudaGetSymbolAddress((void**)&w2lo, g_w2lo);

    cudaFuncSetAttribute(mma_gemm_kernel<CIN>,
                         cudaFuncAttributeMaxDynamicSharedMemorySize, SM_TOT);
    cudaFuncSetAttribute(mma_gemm_kernel<COUT>,
                         cudaFuncAttributeMaxDynamicSharedMemorySize, SM_TOT);

    const int n4_x2 = (N2T * CIN) / 4;
    const int n4_w2 = (COUT * CIN) / 4;
    const int n4_x1 = (N1T * COUT) / 4;
    const int n4_w1 = (COUT * COUT) / 4;
    const dim3 gg2(N2T / 128, COUT / 128);
    const dim3 ggk(64, 4);
    const dim3 gg1(N1T / 128, COUT / 128);
    const int gia = (N1T * 32) / 256;      // interp_add: 1 warp per row

    if (g_hx.ok) {
        // Full-width fork from t=0:
        //   s0: split x1,w1 -> GEMM1 (no interp) -> out
        //   s1: KNN
        //   s2: split x2,w2 -> GEMM2 -> f2
        // Join on s0 -> interp_add (out += gather(f2)).
        cudaEventRecord(g_hx.eF, 0);
        cudaStreamWaitEvent(g_hx.s1, g_hx.eF, 0);
        cudaStreamWaitEvent(g_hx.s2, g_hx.eF, 0);

        // s1: KNN (independent of all GEMM work)
        knn_kernel<<<ggk, 256, 0, g_hx.s1>>>(points_1, rs1, points_2, rs2);
        cudaEventRecord(g_hx.e1, g_hx.s1);

        // s2: GEMM2 chain -> g_f2
        split_bf16_kernel<<<(n4_x2 + 255) / 256, 256, 0, g_hx.s2>>>(
            feat_2, x2hi, x2lo, n4_x2);
        split_bf16_kernel<<<(n4_w2 + 255) / 256, 256, 0, g_hx.s2>>>(
            w2, w2hi, w2lo, n4_w2);
        mma_gemm_kernel<CIN><<<gg2, 256, SM_TOT, g_hx.s2>>>(
            x2hi, x2lo, w2hi, w2lo, b2, g2, be2, m2, v2, f2_ptr);
        cudaEventRecord(g_hx.e2, g_hx.s2);

        // s0: GEMM1 chain -> out (linear1+BN+ReLU part; starts at t=0)
        split_bf16_kernel<<<(n4_x1 + 255) / 256, 256>>>(feat_1, x1hi, x1lo, n4_x1);
        split_bf16_kernel<<<(n4_w1 + 255) / 256, 256>>>(w1, w1hi, w1lo, n4_w1);
        mma_gemm_kernel<COUT><<<gg1, 256, SM_TOT>>>(
            x1hi, x1lo, w1hi, w1lo, b1, g1, be1, m1, v1, out);

        // Join, then out += interp
        cudaStreamWaitEvent(0, g_hx.e1, 0);
        cudaStreamWaitEvent(0, g_hx.e2, 0);
        interp_add_kernel<<<gia, 256>>>(out);
    } else {
        // Serial fallback
        split_bf16_kernel<<<(n4_x2 + 255) / 256, 256>>>(feat_2, x2hi, x2lo, n4_x2);
        split_bf16_kernel<<<(n4_w2 + 255) / 256, 256>>>(w2, w2hi, w2lo, n4_w2);
        split_bf16_kernel<<<(n4_x1 + 255) / 256, 256>>>(feat_1, x1hi, x1lo, n4_x1);
        split_bf16_kernel<<<(n4_w1 + 255) / 256, 256>>>(w1, w1hi, w1lo, n4_w1);
        mma_gemm_kernel<CIN><<<gg2, 256, SM_TOT>>>(
            x2hi, x2lo, w2hi, w2lo, b2, g2, be2, m2, v2, f2_ptr);
        knn_kernel<<<ggk, 256>>>(points_1, rs1, points_2, rs2);
        mma_gemm_kernel<COUT><<<gg1, 256, SM_TOT>>>(
            x1hi, x1lo, w1hi, w1lo, b1, g1, be1, m1, v1, out);
        interp_add_kernel<<<gia, 256>>>(out);
    }
}

// round 16
// speedup vs baseline: 1.6805x; 1.0868x over previous
#include <cuda_runtime.h>
#include <cuda_fp16.h>
#include <math_constants.h>
#include <cstdint>

// Problem constants (fixed by setup_inputs)
#define N1T   65536
#define N2T   16384
#define CIN   512
#define COUT  256
#define BN_EPS 1e-5f

// ---------------- scratch (device globals; no allocs allowed) --------------
__device__ float g_f2[N2T * COUT];            // linear2 output, fp32 (16 MB)
__device__ int   g_knn_idx[N1T * 3];
__device__ float g_knn_w[N1T * 3];
__device__ __half g_x1hi[N1T * COUT];         // feat_1 fp16 split
__device__ __half g_x1lo[N1T * COUT];
__device__ __half g_x2hi[N2T * CIN];          // feat_2 fp16 split
__device__ __half g_x2lo[N2T * CIN];
__device__ __half g_w1hi[COUT * COUT];
__device__ __half g_w1lo[COUT * COUT];        // written, unused (reuse kernel)
__device__ __half g_w2hi[COUT * CIN];
__device__ __half g_w2lo[COUT * CIN];         // written, unused

// ---------------- PTX helpers (baseline ISA only; NO tcgen05) --------------
__device__ __forceinline__ uint32_t smem_u32(const void* p) {
    uint32_t a;
    asm("{ .reg .u64 t; cvta.to.shared.u64 t, %1; cvt.u32.u64 %0, t; }"
        : "=r"(a) : "l"(p));
    return a;
}
__device__ __forceinline__ void cp16(uint32_t saddr, const void* g) {
    asm volatile("cp.async.cg.shared.global [%0], [%1], 16;"
                 :: "r"(saddr), "l"(g) : "memory");
}
__device__ __forceinline__ void cp_commit() {
    asm volatile("cp.async.commit_group;" ::: "memory");
}
template <int N>
__device__ __forceinline__ void cp_wait() {
    asm volatile("cp.async.wait_group %0;" :: "n"(N) : "memory");
}
__device__ __forceinline__ void ldsm4(uint32_t (&r)[4], uint32_t addr) {
    asm volatile("ldmatrix.sync.aligned.m8n8.x4.shared.b16 {%0,%1,%2,%3}, [%4];"
                 : "=r"(r[0]), "=r"(r[1]), "=r"(r[2]), "=r"(r[3]) : "r"(addr));
}
__device__ __forceinline__ void mma16816h(float (&d)[4], const uint32_t (&a)[4],
                                          uint32_t b0, uint32_t b1) {
    asm volatile(
        "mma.sync.aligned.m16n8k16.row.col.f32.f16.f16.f32 "
        "{%0,%1,%2,%3}, {%4,%5,%6,%7}, {%8,%9}, {%0,%1,%2,%3};"
        : "+f"(d[0]), "+f"(d[1]), "+f"(d[2]), "+f"(d[3])
        : "r"(a[0]), "r"(a[1]), "r"(a[2]), "r"(a[3]), "r"(b0), "r"(b1));
}
// 64B-row XOR swizzle: conflict-free ldmatrix with 64B row stride
__device__ __forceinline__ uint32_t sw64(uint32_t off) {
    return off ^ ((off >> 3) & 0x30);
}

// ---------------------------------------------------------------------------
// Split fp32 -> (hi, lo) fp16 pair; hi+lo captures ~22 mantissa bits.
// ---------------------------------------------------------------------------
__global__ void split_fp16_kernel(const float* __restrict__ in,
                                  __half* __restrict__ hi,
                                  __half* __restrict__ lo, int n4) {
    int i = blockIdx.x * blockDim.x + threadIdx.x;
    if (i >= n4) return;
    float4 v = reinterpret_cast<const float4*>(in)[i];
    float vv[4] = {v.x, v.y, v.z, v.w};
    ushort4 h, l;
    unsigned short* hp = &h.x;
    unsigned short* lp = &l.x;
    #pragma unroll
    for (int j = 0; j < 4; ++j) {
        __half hb = __float2half_rn(vv[j]);
        __half lb = __float2half_rn(vv[j] - __half2float(hb));
        hp[j] = __half_as_ushort(hb);
        lp[j] = __half_as_ushort(lb);
    }
    reinterpret_cast<ushort4*>(hi)[i] = h;
    reinterpret_cast<ushort4*>(lo)[i] = l;
}

// ---------------------------------------------------------------------------
// KNN: bit-exact d2 arithmetic (load-bearing for rel_err — do not change):
//   qq = (qx*qx + qy*qy) + qz*qz ; pp likewise
//   dot = fma(qz,pz, fma(qy,py, qx*px))
//   d2  = fma(-2, dot, qq+pp)   [== (qq+pp) - 2*dot exactly: 2*dot is exact,
//                                single final rounding in both forms]
// Strict-< insertion keeps lower index on ties (matches jax.lax.top_k).
// ---------------------------------------------------------------------------
#define KNN_CHUNK 2048

struct Top3 {
    float d0, d1, d2;
    int i0, i1, i2;
};

__device__ __forceinline__ void knn_point(Top3& t3, const float4 p, int gj,
                                          float qx, float qy, float qz, float qq) {
    const float dot = fmaf(qz, p.z, fmaf(qy, p.y, __fmul_rn(qx, p.x)));
    const float s = __fadd_rn(qq, p.w);
    const float t = fmaf(-2.0f, dot, s);
    if (t < t3.d2) {
        if (t < t3.d1) {
            t3.d2 = t3.d1; t3.i2 = t3.i1;
            if (t < t3.d0) { t3.d1 = t3.d0; t3.i1 = t3.i0; t3.d0 = t; t3.i0 = gj; }
            else           { t3.d1 = t; t3.i1 = gj; }
        } else { t3.d2 = t; t3.i2 = gj; }
    }
}

__global__ void knn_kernel(const float* __restrict__ pts1,
                           const int*   __restrict__ rs1,
                           const float* __restrict__ pts2,
                           const int*   __restrict__ rs2) {
    __shared__ float4 sp[KNN_CHUNK];

    const int seg = blockIdx.y;
    const int tid = threadIdx.x;
    const int q_start = rs1[seg], q_end = rs1[seg + 1];
    const int p_start = rs2[seg], p_end = rs2[seg + 1];
    const int nq = q_end - q_start;
    const int np = p_end - p_start;

    const int ql = blockIdx.x * blockDim.x + tid;
    const bool active = ql < nq;
    const int q = q_start + (active ? ql : 0);

    const float qx = pts1[q * 3 + 0];
    const float qy = pts1[q * 3 + 1];
    const float qz = pts1[q * 3 + 2];
    const float qq = __fadd_rn(__fadd_rn(__fmul_rn(qx, qx), __fmul_rn(qy, qy)),
                               __fmul_rn(qz, qz));

    Top3 t3 = {CUDART_INF_F, CUDART_INF_F, CUDART_INF_F, 0, 0, 0};

    for (int cb = 0; cb < np; cb += KNN_CHUNK) {
        const int cnt = min(KNN_CHUNK, np - cb);
        __syncthreads();
        for (int j = tid; j < cnt; j += blockDim.x) {
            const int pi = p_start + cb + j;
            const float px = pts2[pi * 3 + 0];
            const float py = pts2[pi * 3 + 1];
            const float pz = pts2[pi * 3 + 2];
            const float pp = __fadd_rn(
                __fadd_rn(__fmul_rn(px, px), __fmul_rn(py, py)),
                __fmul_rn(pz, pz));
            sp[j] = make_float4(px, py, pz, pp);
        }
        __syncthreads();
        if (active) {
            if (cnt == KNN_CHUNK) {        // fast path: static trip count
                #pragma unroll 8
                for (int j = 0; j < KNN_CHUNK; ++j)
                    knn_point(t3, sp[j], cb + j, qx, qy, qz, qq);
            } else {
                for (int j = 0; j < cnt; ++j)
                    knn_point(t3, sp[j], cb + j, qx, qy, qz, qq);
            }
        }
    }

    if (active) {
        const float e0 = fmaxf(t3.d0, 0.f), e1 = fmaxf(t3.d1, 0.f), e2 = fmaxf(t3.d2, 0.f);
        const float w0 = 1.f / (e0 + 1e-8f);
        const float w1 = 1.f / (e1 + 1e-8f);
        const float w2 = 1.f / (e2 + 1e-8f);
        const float inv = 1.f / (w0 + w1 + w2);
        const int base = q * 3;
        g_knn_idx[base + 0] = p_start + t3.i0;  g_knn_w[base + 0] = w0 * inv;
        g_knn_idx[base + 1] = p_start + t3.i1;  g_knn_w[base + 1] = w1 * inv;
        g_knn_idx[base + 2] = p_start + t3.i2;  g_knn_w[base + 2] = w2 * inv;
    }
}

// ---------------------------------------------------------------------------
// interp_add: out[r, :] += w0*f2[j0,:] + w1*f2[j1,:] + w2*f2[j2,:]
// One warp per row; each lane covers 8 cols as 2 float4 slices.
// ---------------------------------------------------------------------------
__global__ void __launch_bounds__(256)
interp_add_kernel(float* __restrict__ out) {
    const int warp = (blockIdx.x * blockDim.x + threadIdx.x) >> 5;
    const int lane = threadIdx.x & 31;
    const int b3 = warp * 3;
    const int j0 = g_knn_idx[b3 + 0];
    const int j1 = g_knn_idx[b3 + 1];
    const int j2 = g_knn_idx[b3 + 2];
    const float w0 = g_knn_w[b3 + 0];
    const float w1 = g_knn_w[b3 + 1];
    const float w2 = g_knn_w[b3 + 2];
    const float* f0 = &g_f2[(size_t)j0 * COUT];
    const float* f1 = &g_f2[(size_t)j1 * COUT];
    const float* f2v = &g_f2[(size_t)j2 * COUT];
    float* orow = out + (size_t)warp * COUT;
    #pragma unroll
    for (int i = 0; i < 2; ++i) {
        const int c = lane * 4 + i * 128;
        const float4 a = *reinterpret_cast<const float4*>(&f0[c]);
        const float4 b = *reinterpret_cast<const float4*>(&f1[c]);
        const float4 d = *reinterpret_cast<const float4*>(&f2v[c]);
        float4 o = *reinterpret_cast<float4*>(&orow[c]);
        o.x += w0 * a.x + w1 * b.x + w2 * d.x;
        o.y += w0 * a.y + w1 * b.y + w2 * d.y;
        o.z += w0 * a.z + w1 * b.z + w2 * d.z;
        o.w += w0 * a.w + w1 * b.w + w2 * d.w;
        *reinterpret_cast<float4*>(&orow[c]) = o;
    }
}

// ---------------------------------------------------------------------------
// mma.sync 2-term fp16-split GEMM + BN + ReLU.
//   D = Ah*Bh^T + Al*Bh^T    (fp32 accum; A = Ah+Al captures ~22 bits,
//                             B = fp16(w) — w-quantization error ~1e-4 rel)
// CTA tile 128x128, BK=32, 8 warps. 3-stage cp.async ring, 3 tiles/chunk.
// __launch_bounds__(256, 2): 2 CTAs/SM.
// ---------------------------------------------------------------------------
#define TILE_B   8192          // one 128x32-fp16 tile (128 rows x 64 B)
#define BUF_B    (3 * TILE_B)  // Ah, Al, Bh
#define NSTAGE   3
#define SM_COEFF (NSTAGE * BUF_B)
#define SM_TOT   (SM_COEFF + 1024)

template <int KD>
__global__ void __launch_bounds__(256, 2)
mma_gemm_kernel(const __half* __restrict__ Ahi,
                const __half* __restrict__ Alo,
                const __half* __restrict__ Bhi,
                const float* __restrict__ bb, const float* __restrict__ gg,
                const float* __restrict__ be, const float* __restrict__ mm,
                const float* __restrict__ vv,
                float* __restrict__ out) {
    extern __shared__ char smem[];
    const uint32_t sbase = smem_u32(smem);
    const int tid = threadIdx.x;
    const int lane = tid & 31;
    const int wid = tid >> 5;
    const int m0 = blockIdx.x * 128;
    const int c0 = blockIdx.y * 128;

    // BN coefficients for this CTA's 128 output columns
    float* sc_s = reinterpret_cast<float*>(smem + SM_COEFF);
    float* sh_s = sc_s + 128;
    if (tid < 128) {
        const int c = c0 + tid;
        const float s = gg[c] * rsqrtf(vv[c] + BN_EPS);
        sc_s[tid] = s;
        sh_s[tid] = (bb[c] - mm[c]) * s + be[c];
    }

    const __half* srcs[3] = {Ahi, Alo, Bhi};
    const int r0s[3] = {m0, m0, c0};

    auto load_chunk = [&](int chunk, int stage) {
        const int k0 = chunk * 32;
        #pragma unroll
        for (int t = 0; t < 3; ++t) {
            const uint32_t tb = sbase + stage * BUF_B + t * TILE_B;
            #pragma unroll
            for (int i = 0; i < 2; ++i) {
                const int u = tid + i * 256;          // 512 16B units per tile
                const int row = u >> 2;
                const int cu = u & 3;
                cp16(tb + sw64((uint32_t)(row * 64 + cu * 16)),
                     srcs[t] + (size_t)(r0s[t] + row) * KD + k0 + cu * 8);
            }
        }
    };

    float acc[2][8][4];
    #pragma unroll
    for (int a = 0; a < 2; ++a)
        #pragma unroll
        for (int b = 0; b < 8; ++b)
            #pragma unroll
            for (int c = 0; c < 4; ++c) acc[a][b][c] = 0.f;

    const int mw = (wid & 3) * 32;   // warp M offset within CTA tile
    const int nw = (wid >> 2) * 64;  // warp N offset within CTA tile
    const int lr = lane & 15;        // ldmatrix row
    const int lc = (lane >> 4) & 1;  // ldmatrix 16B col half

    constexpr int NCH = KD / 32;
    load_chunk(0, 0); cp_commit();
    load_chunk(1, 1); cp_commit();

    for (int ch = 0; ch < NCH; ++ch) {
        cp_wait<1>();          // group `ch` (and older) complete for THIS thread
        __syncthreads();       // ... and for every thread in the CTA
        const uint32_t bufb = sbase + (ch % NSTAGE) * BUF_B;

        #pragma unroll
        for (int k16 = 0; k16 < 2; ++k16) {
            uint32_t ah[2][4], al[2][4];
            #pragma unroll
            for (int tm = 0; tm < 2; ++tm) {
                const uint32_t sw = sw64(
                    (uint32_t)((mw + tm * 16 + lr) * 64 + k16 * 32 + lc * 16));
                ldsm4(ah[tm], bufb + 0 * TILE_B + sw);
                ldsm4(al[tm], bufb + 1 * TILE_B + sw);
            }
            uint32_t bh[4][4];
            #pragma unroll
            for (int t16 = 0; t16 < 4; ++t16) {
                const uint32_t sw = sw64(
                    (uint32_t)((nw + t16 * 16 + lr) * 64 + k16 * 32 + lc * 16));
                ldsm4(bh[t16], bufb + 2 * TILE_B + sw);
            }
            #pragma unroll
            for (int tm = 0; tm < 2; ++tm)
                #pragma unroll
                for (int tn = 0; tn < 8; ++tn) {
                    const int t16 = tn >> 1, o = tn & 1;
                    mma16816h(acc[tm][tn], ah[tm], bh[t16][o], bh[t16][o + 2]);
                    mma16816h(acc[tm][tn], al[tm], bh[t16][o], bh[t16][o + 2]);
                }
        }

        // Issue loads for stage ch+2 (its buffer was last READ at iter ch-1;
        // the sync above guarantees all warps are past that read).
        if (ch + 2 < NCH) load_chunk(ch + 2, (ch + 2) % NSTAGE);
        cp_commit();           // empty groups at the tail keep counts uniform
    }

    // Epilogue: BN + ReLU. acc[tm][tn][h*2+e] = row m0+mw+tm*16+h*8+g,
    //                                           col c0+nw+tn*8+2*tig+e
    const int g = lane >> 2, tig = lane & 3;
    #pragma unroll
    for (int tm = 0; tm < 2; ++tm) {
        #pragma unroll
        for (int h = 0; h < 2; ++h) {
            const int r = m0 + mw + tm * 16 + h * 8 + g;
            #pragma unroll
            for (int tn = 0; tn < 8; ++tn) {
                const int cl = nw + tn * 8 + 2 * tig;   // local col in [0,128)
                const int gc = c0 + cl;
                float o0 = fmaxf(fmaf(acc[tm][tn][h * 2 + 0], sc_s[cl + 0], sh_s[cl + 0]), 0.f);
                float o1 = fmaxf(fmaf(acc[tm][tn][h * 2 + 1], sc_s[cl + 1], sh_s[cl + 1]), 0.f);
                *reinterpret_cast<float2*>(&out[(size_t)r * COUT + gc]) =
                    make_float2(o0, o1);
            }
        }
    }
}

// ---------------------------------------------------------------------------
// Fork-join stream/event set, created ONCE at static-init time. If anything
// fails, ok stays false and kernel_launch uses the serial path.
// ---------------------------------------------------------------------------
namespace {
struct HxStreams {
    cudaStream_t s1 = nullptr, s2 = nullptr;
    cudaEvent_t eF = nullptr, e1 = nullptr, e2 = nullptr;
    bool ok = false;
    HxStreams() {
        ok = (cudaStreamCreateWithFlags(&s1, cudaStreamNonBlocking) == cudaSuccess) &&
             (cudaStreamCreateWithFlags(&s2, cudaStreamNonBlocking) == cudaSuccess) &&
             (cudaEventCreateWithFlags(&eF, cudaEventDisableTiming) == cudaSuccess) &&
             (cudaEventCreateWithFlags(&e1, cudaEventDisableTiming) == cudaSuccess) &&
             (cudaEventCreateWithFlags(&e2, cudaEventDisableTiming) == cudaSuccess);
    }
};
HxStreams g_hx;
}  // namespace

// ---------------------------------------------------------------------------
extern "C" void kernel_launch(void* const* d_in, const int* in_sizes, int n_in,
                              void* d_out, int out_size) {
    const float* points_1 = (const float*)d_in[0];
    const float* feat_1   = (const float*)d_in[1];
    const int*   rs1      = (const int*)  d_in[2];
    const float* points_2 = (const float*)d_in[3];
    const float* feat_2   = (const float*)d_in[4];
    const int*   rs2      = (const int*)  d_in[5];
    const float* w1  = (const float*)d_in[6];
    const float* b1  = (const float*)d_in[7];
    const float* g1  = (const float*)d_in[8];
    const float* be1 = (const float*)d_in[9];
    const float* m1  = (const float*)d_in[10];
    const float* v1  = (const float*)d_in[11];
    const float* w2  = (const float*)d_in[12];
    const float* b2  = (const float*)d_in[13];
    const float* g2  = (const float*)d_in[14];
    const float* be2 = (const float*)d_in[15];
    const float* m2  = (const float*)d_in[16];
    const float* v2  = (const float*)d_in[17];
    float* out = (float*)d_out;

    float* f2_ptr;        cudaGetSymbolAddress((void**)&f2_ptr, g_f2);
    __half *x1hi, *x1lo, *x2hi, *x2lo, *w1hi, *w1lo, *w2hi, *w2lo;
    cudaGetSymbolAddress((void**)&x1hi, g_x1hi);
    cudaGetSymbolAddress((void**)&x1lo, g_x1lo);
    cudaGetSymbolAddress((void**)&x2hi, g_x2hi);
    cudaGetSymbolAddress((void**)&x2lo, g_x2lo);
    cudaGetSymbolAddress((void**)&w1hi, g_w1hi);
    cudaGetSymbolAddress((void**)&w1lo, g_w1lo);
    cudaGetSymbolAddress((void**)&w2hi, g_w2hi);
    cudaGetSymbolAddress((void**)&w2lo, g_w2lo);

    cudaFuncSetAttribute(mma_gemm_kernel<CIN>,
                         cudaFuncAttributeMaxDynamicSharedMemorySize, SM_TOT);
    cudaFuncSetAttribute(mma_gemm_kernel<COUT>,
                         cudaFuncAttributeMaxDynamicSharedMemorySize, SM_TOT);

    const int n4_x2 = (N2T * CIN) / 4;
    const int n4_w2 = (COUT * CIN) / 4;
    const int n4_x1 = (N1T * COUT) / 4;
    const int n4_w1 = (COUT * COUT) / 4;
    const dim3 gg2(N2T / 128, COUT / 128);
    const dim3 ggk(64, 4);
    const dim3 gg1(N1T / 128, COUT / 128);
    const int gia = (N1T * 32) / 256;      // interp_add: 1 warp per row

    if (g_hx.ok) {
        // Full-width fork from t=0:
        //   s0: split x1,w1 -> GEMM1 (no interp) -> out
        //   s1: KNN
        //   s2: split x2,w2 -> GEMM2 -> f2
        // Join on s0 -> interp_add (out += gather(f2)).
        cudaEventRecord(g_hx.eF, 0);
        cudaStreamWaitEvent(g_hx.s1, g_hx.eF, 0);
        cudaStreamWaitEvent(g_hx.s2, g_hx.eF, 0);

        // s1: KNN (independent of all GEMM work)
        knn_kernel<<<ggk, 256, 0, g_hx.s1>>>(points_1, rs1, points_2, rs2);
        cudaEventRecord(g_hx.e1, g_hx.s1);

        // s2: GEMM2 chain -> g_f2
        split_fp16_kernel<<<(n4_x2 + 255) / 256, 256, 0, g_hx.s2>>>(
            feat_2, x2hi, x2lo, n4_x2);
        split_fp16_kernel<<<(n4_w2 + 255) / 256, 256, 0, g_hx.s2>>>(
            w2, w2hi, w2lo, n4_w2);
        mma_gemm_kernel<CIN><<<gg2, 256, SM_TOT, g_hx.s2>>>(
            x2hi, x2lo, w2hi, b2, g2, be2, m2, v2, f2_ptr);
        cudaEventRecord(g_hx.e2, g_hx.s2);

        // s0: GEMM1 chain -> out (linear1+BN+ReLU part; starts at t=0)
        split_fp16_kernel<<<(n4_x1 + 255) / 256, 256>>>(feat_1, x1hi, x1lo, n4_x1);
        split_fp16_kernel<<<(n4_w1 + 255) / 256, 256>>>(w1, w1hi, w1lo, n4_w1);
        mma_gemm_kernel<COUT><<<gg1, 256, SM_TOT>>>(
            x1hi, x1lo, w1hi, b1, g1, be1, m1, v1, out);

        // Join, then out += interp
        cudaStreamWaitEvent(0, g_hx.e1, 0);
        cudaStreamWaitEvent(0, g_hx.e2, 0);
        interp_add_kernel<<<gia, 256>>>(out);
    } else {
        // Serial fallback
        split_fp16_kernel<<<(n4_x2 + 255) / 256, 256>>>(feat_2, x2hi, x2lo, n4_x2);
        split_fp16_kernel<<<(n4_w2 + 255) / 256, 256>>>(w2, w2hi, w2lo, n4_w2);
        split_fp16_kernel<<<(n4_x1 + 255) / 256, 256>>>(feat_1, x1hi, x1lo, n4_x1);
        split_fp16_kernel<<<(n4_w1 + 255) / 256, 256>>>(w1, w1hi, w1lo, n4_w1);
        mma_gemm_kernel<CIN><<<gg2, 256, SM_TOT>>>(
            x2hi, x2lo, w2hi, b2, g2, be2, m2, v2, f2_ptr);
        knn_kernel<<<ggk, 256>>>(points_1, rs1, points_2, rs2);
        mma_gemm_kernel<COUT><<<gg1, 256, SM_TOT>>>(
            x1hi, x1lo, w1hi, b1, g1, be1, m1, v1, out);
        interp_add_kernel<<<gia, 256>>>(out);
    }
}

// round 17
// speedup vs baseline: 1.6947x; 1.0085x over previous
#include <cuda_runtime.h>
#include <cuda_fp16.h>
#include <math_constants.h>
#include <cstdint>

// Problem constants (fixed by setup_inputs)
#define N1T   65536
#define N2T   16384
#define CIN   512
#define COUT  256
#define BN_EPS 1e-5f

#define GRID_R  16                 // 16x16x16 cells per segment
#define NCELL   (GRID_R * GRID_R * GRID_R)
#define CELL_H  0.625f             // 10.0 / 16
#define INV_H   1.6f               // 16 / 10

// ---------------- scratch (device globals; no allocs allowed) --------------
__device__ float g_f2[N2T * COUT];            // linear2 output, fp32 (16 MB)
__device__ int   g_knn_idx[N1T * 3];
__device__ float g_knn_w[N1T * 3];
__device__ __half g_x1hi[N1T * COUT];         // feat_1 fp16 split
__device__ __half g_x1lo[N1T * COUT];
__device__ __half g_x2hi[N2T * CIN];          // feat_2 fp16 split
__device__ __half g_x2lo[N2T * CIN];
__device__ __half g_w1hi[COUT * COUT];
__device__ __half g_w1lo[COUT * COUT];        // written, unused (reuse kernel)
__device__ __half g_w2hi[COUT * CIN];
__device__ __half g_w2lo[COUT * CIN];         // written, unused
// KNN spatial grid (per segment)
__device__ int    g_cell_cnt[4 * NCELL];
__device__ int    g_cell_cur[4 * NCELL];
__device__ int    g_cell_start[4 * (NCELL + 1)];
__device__ float4 g_spts[4 * 4096];           // cell-sorted (x,y,z,pp)
__device__ int    g_sidx[4 * 4096];           // original in-segment index

// ---------------- PTX helpers (baseline ISA only; NO tcgen05) --------------
__device__ __forceinline__ uint32_t smem_u32(const void* p) {
    uint32_t a;
    asm("{ .reg .u64 t; cvta.to.shared.u64 t, %1; cvt.u32.u64 %0, t; }"
        : "=r"(a) : "l"(p));
    return a;
}
__device__ __forceinline__ void cp16(uint32_t saddr, const void* g) {
    asm volatile("cp.async.cg.shared.global [%0], [%1], 16;"
                 :: "r"(saddr), "l"(g) : "memory");
}
__device__ __forceinline__ void cp_commit() {
    asm volatile("cp.async.commit_group;" ::: "memory");
}
template <int N>
__device__ __forceinline__ void cp_wait() {
    asm volatile("cp.async.wait_group %0;" :: "n"(N) : "memory");
}
__device__ __forceinline__ void ldsm4(uint32_t (&r)[4], uint32_t addr) {
    asm volatile("ldmatrix.sync.aligned.m8n8.x4.shared.b16 {%0,%1,%2,%3}, [%4];"
                 : "=r"(r[0]), "=r"(r[1]), "=r"(r[2]), "=r"(r[3]) : "r"(addr));
}
__device__ __forceinline__ void mma16816h(float (&d)[4], const uint32_t (&a)[4],
                                          uint32_t b0, uint32_t b1) {
    asm volatile(
        "mma.sync.aligned.m16n8k16.row.col.f32.f16.f16.f32 "
        "{%0,%1,%2,%3}, {%4,%5,%6,%7}, {%8,%9}, {%0,%1,%2,%3};"
        : "+f"(d[0]), "+f"(d[1]), "+f"(d[2]), "+f"(d[3])
        : "r"(a[0]), "r"(a[1]), "r"(a[2]), "r"(a[3]), "r"(b0), "r"(b1));
}
// 64B-row XOR swizzle: conflict-free ldmatrix with 64B row stride
__device__ __forceinline__ uint32_t sw64(uint32_t off) {
    return off ^ ((off >> 3) & 0x30);
}

// ---------------------------------------------------------------------------
// Split fp32 -> (hi, lo) fp16 pair; hi+lo captures ~22 mantissa bits.
// ---------------------------------------------------------------------------
__global__ void split_fp16_kernel(const float* __restrict__ in,
                                  __half* __restrict__ hi,
                                  __half* __restrict__ lo, int n4) {
    int i = blockIdx.x * blockDim.x + threadIdx.x;
    if (i >= n4) return;
    float4 v = reinterpret_cast<const float4*>(in)[i];
    float vv[4] = {v.x, v.y, v.z, v.w};
    ushort4 h, l;
    unsigned short* hp = &h.x;
    unsigned short* lp = &l.x;
    #pragma unroll
    for (int j = 0; j < 4; ++j) {
        __half hb = __float2half_rn(vv[j]);
        __half lb = __float2half_rn(vv[j] - __half2float(hb));
        hp[j] = __half_as_ushort(hb);
        lp[j] = __half_as_ushort(lb);
    }
    reinterpret_cast<ushort4*>(hi)[i] = h;
    reinterpret_cast<ushort4*>(lo)[i] = l;
}

// ---------------------------------------------------------------------------
// KNN via spatial grid. Per-pair arithmetic is IDENTICAL to the validated
// brute-force version:
//   qq = (qx*qx + qy*qy) + qz*qz ; pp likewise (computed at scatter time)
//   dot = fma(qz,pz, fma(qy,py, qx*px)) ; t = fma(-2, dot, rn(qq+pp))
// Selection is lexicographic (value, original index) via explicit tie-breaks
// == jax.lax.top_k semantics, independent of scan order (so the
// nondeterministic atomic scatter order inside a cell cannot change results).
// Stop bound: unexamined points have true d^2 >= bmin^2; computed-d2 abs
// error <= ~2.4e-4, so stop only when d2_3rd < bmin^2 - 1e-3.
// ---------------------------------------------------------------------------
__device__ __forceinline__ int cell_of(float x) {
    int c = (int)(x * INV_H);
    return min(GRID_R - 1, max(0, c));
}

__global__ void grid_zero_kernel() {
    int i = blockIdx.x * blockDim.x + threadIdx.x;
    if (i < 4 * NCELL) g_cell_cnt[i] = 0;
}

__global__ void grid_count_kernel(const float* __restrict__ pts2,
                                  const int* __restrict__ rs2) {
    const int seg = blockIdx.y;
    const int p_start = rs2[seg], p_end = rs2[seg + 1];
    const int np = p_end - p_start;
    const int i = blockIdx.x * blockDim.x + threadIdx.x;
    if (i >= np) return;
    const float px = pts2[(size_t)(p_start + i) * 3 + 0];
    const float py = pts2[(size_t)(p_start + i) * 3 + 1];
    const float pz = pts2[(size_t)(p_start + i) * 3 + 2];
    const int c = (cell_of(pz) * GRID_R + cell_of(py)) * GRID_R + cell_of(px);
    atomicAdd(&g_cell_cnt[seg * NCELL + c], 1);
}

__global__ void grid_scan_kernel() {
    __shared__ int bsum[256];
    const int seg = blockIdx.x;
    const int t = threadIdx.x;
    const int base = seg * NCELL;
    int local[16];
    int s = 0;
    #pragma unroll
    for (int i = 0; i < 16; ++i) {
        local[i] = s;
        s += g_cell_cnt[base + t * 16 + i];
    }
    bsum[t] = s;
    __syncthreads();
    for (int off = 1; off < 256; off <<= 1) {
        int v = (t >= off) ? bsum[t - off] : 0;
        __syncthreads();
        bsum[t] += v;
        __syncthreads();
    }
    const int excl = (t == 0) ? 0 : bsum[t - 1];
    #pragma unroll
    for (int i = 0; i < 16; ++i) {
        const int st = excl + local[i];
        g_cell_start[seg * (NCELL + 1) + t * 16 + i] = st;
        g_cell_cur[base + t * 16 + i] = st;
    }
    if (t == 255) g_cell_start[seg * (NCELL + 1) + NCELL] = bsum[255];
}

__global__ void grid_scatter_kernel(const float* __restrict__ pts2,
                                    const int* __restrict__ rs2) {
    const int seg = blockIdx.y;
    const int p_start = rs2[seg], p_end = rs2[seg + 1];
    const int np = p_end - p_start;
    const int i = blockIdx.x * blockDim.x + threadIdx.x;
    if (i >= np) return;
    const float px = pts2[(size_t)(p_start + i) * 3 + 0];
    const float py = pts2[(size_t)(p_start + i) * 3 + 1];
    const float pz = pts2[(size_t)(p_start + i) * 3 + 2];
    const float pp = __fadd_rn(
        __fadd_rn(__fmul_rn(px, px), __fmul_rn(py, py)), __fmul_rn(pz, pz));
    const int c = (cell_of(pz) * GRID_R + cell_of(py)) * GRID_R + cell_of(px);
    const int pos = atomicAdd(&g_cell_cur[seg * NCELL + c], 1);
    g_spts[seg * 4096 + pos] = make_float4(px, py, pz, pp);
    g_sidx[seg * 4096 + pos] = i;
}

__global__ void knn_grid_kernel(const float* __restrict__ pts1,
                                const int* __restrict__ rs1,
                                const int* __restrict__ rs2) {
    const int seg = blockIdx.y;
    const int q_start = rs1[seg], q_end = rs1[seg + 1];
    const int p_start = rs2[seg];
    const int nq = q_end - q_start;
    const int ql = blockIdx.x * blockDim.x + threadIdx.x;
    if (ql >= nq) return;
    const int q = q_start + ql;

    const float qx = pts1[(size_t)q * 3 + 0];
    const float qy = pts1[(size_t)q * 3 + 1];
    const float qz = pts1[(size_t)q * 3 + 2];
    const float qq = __fadd_rn(__fadd_rn(__fmul_rn(qx, qx), __fmul_rn(qy, qy)),
                               __fmul_rn(qz, qz));
    const int cx = cell_of(qx), cy = cell_of(qy), cz = cell_of(qz);

    const float4* __restrict__ spts = g_spts + seg * 4096;
    const int* __restrict__ sidx = g_sidx + seg * 4096;
    const int* __restrict__ cst = g_cell_start + seg * (NCELL + 1);

    float d0 = CUDART_INF_F, d1 = CUDART_INF_F, d2v = CUDART_INF_F;
    int i0 = 0, i1 = 0, i2 = 0;

    for (int r = 0; r < GRID_R; ++r) {
        const int xlo = max(cx - r, 0), xhi = min(cx + r, GRID_R - 1);
        const int ylo = max(cy - r, 0), yhi = min(cy + r, GRID_R - 1);
        const int zlo = max(cz - r, 0), zhi = min(cz + r, GRID_R - 1);
        for (int z = zlo; z <= zhi; ++z) {
            const int az = abs(z - cz);
            for (int y = ylo; y <= yhi; ++y) {
                const int ay = abs(y - cy);
                const int chyz = max(az, ay);
                for (int x = xlo; x <= xhi; ++x) {
                    if (max(chyz, abs(x - cx)) != r) continue;  // shell only
                    const int c = (z * GRID_R + y) * GRID_R + x;
                    const int cs = cst[c], ce = cst[c + 1];
                    for (int i = cs; i < ce; ++i) {
                        const float4 p = spts[i];
                        const int gi = sidx[i];
                        const float dot = fmaf(qz, p.z,
                                               fmaf(qy, p.y, __fmul_rn(qx, p.x)));
                        const float t = fmaf(-2.0f, dot, __fadd_rn(qq, p.w));
                        // lexicographic (value, index) top-3 insert
                        if (t < d2v || (t == d2v && gi < i2)) {
                            if (t < d1 || (t == d1 && gi < i1)) {
                                d2v = d1; i2 = i1;
                                if (t < d0 || (t == d0 && gi < i0)) {
                                    d1 = d0; i1 = i0; d0 = t; i0 = gi;
                                } else { d1 = t; i1 = gi; }
                            } else { d2v = t; i2 = gi; }
                        }
                    }
                }
            }
        }
        // Termination
        const bool full = (cx - r <= 0) && (cx + r >= GRID_R - 1) &&
                          (cy - r <= 0) && (cy + r >= GRID_R - 1) &&
                          (cz - r <= 0) && (cz + r >= GRID_R - 1);
        if (full) break;
        if (d2v < CUDART_INF_F) {
            const float fxlo = (cx - r <= 0) ? CUDART_INF_F
                               : qx - (float)(cx - r) * CELL_H;
            const float fxhi = (cx + r >= GRID_R - 1) ? CUDART_INF_F
                               : (float)(cx + r + 1) * CELL_H - qx;
            const float fylo = (cy - r <= 0) ? CUDART_INF_F
                               : qy - (float)(cy - r) * CELL_H;
            const float fyhi = (cy + r >= GRID_R - 1) ? CUDART_INF_F
                               : (float)(cy + r + 1) * CELL_H - qy;
            const float fzlo = (cz - r <= 0) ? CUDART_INF_F
                               : qz - (float)(cz - r) * CELL_H;
            const float fzhi = (cz + r >= GRID_R - 1) ? CUDART_INF_F
                               : (float)(cz + r + 1) * CELL_H - qz;
            const float b = fminf(fminf(fminf(fxlo, fxhi), fminf(fylo, fyhi)),
                                  fminf(fzlo, fzhi));
            if (d2v < b * b - 1e-3f) break;
        }
    }

    const float e0 = fmaxf(d0, 0.f), e1 = fmaxf(d1, 0.f), e2 = fmaxf(d2v, 0.f);
    const float w0 = 1.f / (e0 + 1e-8f);
    const float w1 = 1.f / (e1 + 1e-8f);
    const float w2 = 1.f / (e2 + 1e-8f);
    const float inv = 1.f / (w0 + w1 + w2);
    const int base = q * 3;
    g_knn_idx[base + 0] = p_start + i0;  g_knn_w[base + 0] = w0 * inv;
    g_knn_idx[base + 1] = p_start + i1;  g_knn_w[base + 1] = w1 * inv;
    g_knn_idx[base + 2] = p_start + i2;  g_knn_w[base + 2] = w2 * inv;
}

// ---------------------------------------------------------------------------
// interp_add: out[r, :] += w0*f2[j0,:] + w1*f2[j1,:] + w2*f2[j2,:]
// One warp per row; each lane covers 8 cols as 2 float4 slices.
// ---------------------------------------------------------------------------
__global__ void __launch_bounds__(256)
interp_add_kernel(float* __restrict__ out) {
    const int warp = (blockIdx.x * blockDim.x + threadIdx.x) >> 5;
    const int lane = threadIdx.x & 31;
    const int b3 = warp * 3;
    const int j0 = g_knn_idx[b3 + 0];
    const int j1 = g_knn_idx[b3 + 1];
    const int j2 = g_knn_idx[b3 + 2];
    const float w0 = g_knn_w[b3 + 0];
    const float w1 = g_knn_w[b3 + 1];
    const float w2 = g_knn_w[b3 + 2];
    const float* f0 = &g_f2[(size_t)j0 * COUT];
    const float* f1 = &g_f2[(size_t)j1 * COUT];
    const float* f2v = &g_f2[(size_t)j2 * COUT];
    float* orow = out + (size_t)warp * COUT;
    #pragma unroll
    for (int i = 0; i < 2; ++i) {
        const int c = lane * 4 + i * 128;
        const float4 a = *reinterpret_cast<const float4*>(&f0[c]);
        const float4 b = *reinterpret_cast<const float4*>(&f1[c]);
        const float4 d = *reinterpret_cast<const float4*>(&f2v[c]);
        float4 o = *reinterpret_cast<float4*>(&orow[c]);
        o.x += w0 * a.x + w1 * b.x + w2 * d.x;
        o.y += w0 * a.y + w1 * b.y + w2 * d.y;
        o.z += w0 * a.z + w1 * b.z + w2 * d.z;
        o.w += w0 * a.w + w1 * b.w + w2 * d.w;
        *reinterpret_cast<float4*>(&orow[c]) = o;
    }
}

// ---------------------------------------------------------------------------
// mma.sync 2-term fp16-split GEMM + BN + ReLU.
//   D = Ah*Bh^T + Al*Bh^T    (fp32 accum; A = Ah+Al captures ~22 bits,
//                             B = fp16(w) — w-quantization error ~1e-4 rel)
// CTA tile 128x128, BK=32, 8 warps. 3-stage cp.async ring, 3 tiles/chunk.
// __launch_bounds__(256, 2): 2 CTAs/SM.
// ---------------------------------------------------------------------------
#define TILE_B   8192          // one 128x32-fp16 tile (128 rows x 64 B)
#define BUF_B    (3 * TILE_B)  // Ah, Al, Bh
#define NSTAGE   3
#define SM_COEFF (NSTAGE * BUF_B)
#define SM_TOT   (SM_COEFF + 1024)

template <int KD>
__global__ void __launch_bounds__(256, 2)
mma_gemm_kernel(const __half* __restrict__ Ahi,
                const __half* __restrict__ Alo,
                const __half* __restrict__ Bhi,
                const float* __restrict__ bb, const float* __restrict__ gg,
                const float* __restrict__ be, const float* __restrict__ mm,
                const float* __restrict__ vv,
                float* __restrict__ out) {
    extern __shared__ char smem[];
    const uint32_t sbase = smem_u32(smem);
    const int tid = threadIdx.x;
    const int lane = tid & 31;
    const int wid = tid >> 5;
    const int m0 = blockIdx.x * 128;
    const int c0 = blockIdx.y * 128;

    // BN coefficients for this CTA's 128 output columns
    float* sc_s = reinterpret_cast<float*>(smem + SM_COEFF);
    float* sh_s = sc_s + 128;
    if (tid < 128) {
        const int c = c0 + tid;
        const float s = gg[c] * rsqrtf(vv[c] + BN_EPS);
        sc_s[tid] = s;
        sh_s[tid] = (bb[c] - mm[c]) * s + be[c];
    }

    const __half* srcs[3] = {Ahi, Alo, Bhi};
    const int r0s[3] = {m0, m0, c0};

    auto load_chunk = [&](int chunk, int stage) {
        const int k0 = chunk * 32;
        #pragma unroll
        for (int t = 0; t < 3; ++t) {
            const uint32_t tb = sbase + stage * BUF_B + t * TILE_B;
            #pragma unroll
            for (int i = 0; i < 2; ++i) {
                const int u = tid + i * 256;          // 512 16B units per tile
                const int row = u >> 2;
                const int cu = u & 3;
                cp16(tb + sw64((uint32_t)(row * 64 + cu * 16)),
                     srcs[t] + (size_t)(r0s[t] + row) * KD + k0 + cu * 8);
            }
        }
    };

    float acc[2][8][4];
    #pragma unroll
    for (int a = 0; a < 2; ++a)
        #pragma unroll
        for (int b = 0; b < 8; ++b)
            #pragma unroll
            for (int c = 0; c < 4; ++c) acc[a][b][c] = 0.f;

    const int mw = (wid & 3) * 32;   // warp M offset within CTA tile
    const int nw = (wid >> 2) * 64;  // warp N offset within CTA tile
    const int lr = lane & 15;        // ldmatrix row
    const int lc = (lane >> 4) & 1;  // ldmatrix 16B col half

    constexpr int NCH = KD / 32;
    load_chunk(0, 0); cp_commit();
    load_chunk(1, 1); cp_commit();

    for (int ch = 0; ch < NCH; ++ch) {
        cp_wait<1>();          // group `ch` (and older) complete for THIS thread
        __syncthreads();       // ... and for every thread in the CTA
        const uint32_t bufb = sbase + (ch % NSTAGE) * BUF_B;

        #pragma unroll
        for (int k16 = 0; k16 < 2; ++k16) {
            uint32_t ah[2][4], al[2][4];
            #pragma unroll
            for (int tm = 0; tm < 2; ++tm) {
                const uint32_t sw = sw64(
                    (uint32_t)((mw + tm * 16 + lr) * 64 + k16 * 32 + lc * 16));
                ldsm4(ah[tm], bufb + 0 * TILE_B + sw);
                ldsm4(al[tm], bufb + 1 * TILE_B + sw);
            }
            uint32_t bh[4][4];
            #pragma unroll
            for (int t16 = 0; t16 < 4; ++t16) {
                const uint32_t sw = sw64(
                    (uint32_t)((nw + t16 * 16 + lr) * 64 + k16 * 32 + lc * 16));
                ldsm4(bh[t16], bufb + 2 * TILE_B + sw);
            }
            #pragma unroll
            for (int tm = 0; tm < 2; ++tm)
                #pragma unroll
                for (int tn = 0; tn < 8; ++tn) {
                    const int t16 = tn >> 1, o = tn & 1;
                    mma16816h(acc[tm][tn], ah[tm], bh[t16][o], bh[t16][o + 2]);
                    mma16816h(acc[tm][tn], al[tm], bh[t16][o], bh[t16][o + 2]);
                }
        }

        // Issue loads for stage ch+2 (its buffer was last READ at iter ch-1;
        // the sync above guarantees all warps are past that read).
        if (ch + 2 < NCH) load_chunk(ch + 2, (ch + 2) % NSTAGE);
        cp_commit();           // empty groups at the tail keep counts uniform
    }

    // Epilogue: BN + ReLU. acc[tm][tn][h*2+e] = row m0+mw+tm*16+h*8+g,
    //                                           col c0+nw+tn*8+2*tig+e
    const int g = lane >> 2, tig = lane & 3;
    #pragma unroll
    for (int tm = 0; tm < 2; ++tm) {
        #pragma unroll
        for (int h = 0; h < 2; ++h) {
            const int r = m0 + mw + tm * 16 + h * 8 + g;
            #pragma unroll
            for (int tn = 0; tn < 8; ++tn) {
                const int cl = nw + tn * 8 + 2 * tig;   // local col in [0,128)
                const int gc = c0 + cl;
                float o0 = fmaxf(fmaf(acc[tm][tn][h * 2 + 0], sc_s[cl + 0], sh_s[cl + 0]), 0.f);
                float o1 = fmaxf(fmaf(acc[tm][tn][h * 2 + 1], sc_s[cl + 1], sh_s[cl + 1]), 0.f);
                *reinterpret_cast<float2*>(&out[(size_t)r * COUT + gc]) =
                    make_float2(o0, o1);
            }
        }
    }
}

// ---------------------------------------------------------------------------
// Fork-join stream/event set, created ONCE at static-init time. If anything
// fails, ok stays false and kernel_launch uses the serial path.
// ---------------------------------------------------------------------------
namespace {
struct HxStreams {
    cudaStream_t s1 = nullptr, s2 = nullptr;
    cudaEvent_t eF = nullptr, e1 = nullptr, e2 = nullptr;
    bool ok = false;
    HxStreams() {
        ok = (cudaStreamCreateWithFlags(&s1, cudaStreamNonBlocking) == cudaSuccess) &&
             (cudaStreamCreateWithFlags(&s2, cudaStreamNonBlocking) == cudaSuccess) &&
             (cudaEventCreateWithFlags(&eF, cudaEventDisableTiming) == cudaSuccess) &&
             (cudaEventCreateWithFlags(&e1, cudaEventDisableTiming) == cudaSuccess) &&
             (cudaEventCreateWithFlags(&e2, cudaEventDisableTiming) == cudaSuccess);
    }
};
HxStreams g_hx;
}  // namespace

static inline void launch_knn(cudaStream_t st, const float* points_1,
                              const int* rs1, const float* points_2,
                              const int* rs2) {
    grid_zero_kernel<<<(4 * NCELL + 255) / 256, 256, 0, st>>>();
    {
        dim3 gc((4096 + 255) / 256, 4);
        grid_count_kernel<<<gc, 256, 0, st>>>(points_2, rs2);
    }
    grid_scan_kernel<<<4, 256, 0, st>>>();
    {
        dim3 gs((4096 + 255) / 256, 4);
        grid_scatter_kernel<<<gs, 256, 0, st>>>(points_2, rs2);
    }
    {
        dim3 gq(64, 4);
        knn_grid_kernel<<<gq, 256, 0, st>>>(points_1, rs1, rs2);
    }
}

// ---------------------------------------------------------------------------
extern "C" void kernel_launch(void* const* d_in, const int* in_sizes, int n_in,
                              void* d_out, int out_size) {
    const float* points_1 = (const float*)d_in[0];
    const float* feat_1   = (const float*)d_in[1];
    const int*   rs1      = (const int*)  d_in[2];
    const float* points_2 = (const float*)d_in[3];
    const float* feat_2   = (const float*)d_in[4];
    const int*   rs2      = (const int*)  d_in[5];
    const float* w1  = (const float*)d_in[6];
    const float* b1  = (const float*)d_in[7];
    const float* g1  = (const float*)d_in[8];
    const float* be1 = (const float*)d_in[9];
    const float* m1  = (const float*)d_in[10];
    const float* v1  = (const float*)d_in[11];
    const float* w2  = (const float*)d_in[12];
    const float* b2  = (const float*)d_in[13];
    const float* g2  = (const float*)d_in[14];
    const float* be2 = (const float*)d_in[15];
    const float* m2  = (const float*)d_in[16];
    const float* v2  = (const float*)d_in[17];
    float* out = (float*)d_out;

    float* f2_ptr;        cudaGetSymbolAddress((void**)&f2_ptr, g_f2);
    __half *x1hi, *x1lo, *x2hi, *x2lo, *w1hi, *w1lo, *w2hi, *w2lo;
    cudaGetSymbolAddress((void**)&x1hi, g_x1hi);
    cudaGetSymbolAddress((void**)&x1lo, g_x1lo);
    cudaGetSymbolAddress((void**)&x2hi, g_x2hi);
    cudaGetSymbolAddress((void**)&x2lo, g_x2lo);
    cudaGetSymbolAddress((void**)&w1hi, g_w1hi);
    cudaGetSymbolAddress((void**)&w1lo, g_w1lo);
    cudaGetSymbolAddress((void**)&w2hi, g_w2hi);
    cudaGetSymbolAddress((void**)&w2lo, g_w2lo);

    cudaFuncSetAttribute(mma_gemm_kernel<CIN>,
                         cudaFuncAttributeMaxDynamicSharedMemorySize, SM_TOT);
    cudaFuncSetAttribute(mma_gemm_kernel<COUT>,
                         cudaFuncAttributeMaxDynamicSharedMemorySize, SM_TOT);

    const int n4_x2 = (N2T * CIN) / 4;
    const int n4_w2 = (COUT * CIN) / 4;
    const int n4_x1 = (N1T * COUT) / 4;
    const int n4_w1 = (COUT * COUT) / 4;
    const dim3 gg2(N2T / 128, COUT / 128);
    const dim3 gg1(N1T / 128, COUT / 128);
    const int gia = (N1T * 32) / 256;      // interp_add: 1 warp per row

    if (g_hx.ok) {
        // Full-width fork from t=0:
        //   s0: split x1,w1 -> GEMM1 (no interp) -> out
        //   s1: KNN grid build + query
        //   s2: split x2,w2 -> GEMM2 -> f2
        // Join on s0 -> interp_add (out += gather(f2)).
        cudaEventRecord(g_hx.eF, 0);
        cudaStreamWaitEvent(g_hx.s1, g_hx.eF, 0);
        cudaStreamWaitEvent(g_hx.s2, g_hx.eF, 0);

        // s1: KNN (independent of all GEMM work)
        launch_knn(g_hx.s1, points_1, rs1, points_2, rs2);
        cudaEventRecord(g_hx.e1, g_hx.s1);

        // s2: GEMM2 chain -> g_f2
        split_fp16_kernel<<<(n4_x2 + 255) / 256, 256, 0, g_hx.s2>>>(
            feat_2, x2hi, x2lo, n4_x2);
        split_fp16_kernel<<<(n4_w2 + 255) / 256, 256, 0, g_hx.s2>>>(
            w2, w2hi, w2lo, n4_w2);
        mma_gemm_kernel<CIN><<<gg2, 256, SM_TOT, g_hx.s2>>>(
            x2hi, x2lo, w2hi, b2, g2, be2, m2, v2, f2_ptr);
        cudaEventRecord(g_hx.e2, g_hx.s2);

        // s0: GEMM1 chain -> out (linear1+BN+ReLU part; starts at t=0)
        split_fp16_kernel<<<(n4_x1 + 255) / 256, 256>>>(feat_1, x1hi, x1lo, n4_x1);
        split_fp16_kernel<<<(n4_w1 + 255) / 256, 256>>>(w1, w1hi, w1lo, n4_w1);
        mma_gemm_kernel<COUT><<<gg1, 256, SM_TOT>>>(
            x1hi, x1lo, w1hi, b1, g1, be1, m1, v1, out);

        // Join, then out += interp
        cudaStreamWaitEvent(0, g_hx.e1, 0);
        cudaStreamWaitEvent(0, g_hx.e2, 0);
        interp_add_kernel<<<gia, 256>>>(out);
    } else {
        // Serial fallback
        split_fp16_kernel<<<(n4_x2 + 255) / 256, 256>>>(feat_2, x2hi, x2lo, n4_x2);
        split_fp16_kernel<<<(n4_w2 + 255) / 256, 256>>>(w2, w2hi, w2lo, n4_w2);
        split_fp16_kernel<<<(n4_x1 + 255) / 256, 256>>>(feat_1, x1hi, x1lo, n4_x1);
        split_fp16_kernel<<<(n4_w1 + 255) / 256, 256>>>(w1, w1hi, w1lo, n4_w1);
        mma_gemm_kernel<CIN><<<gg2, 256, SM_TOT>>>(
            x2hi, x2lo, w2hi, b2, g2, be2, m2, v2, f2_ptr);
        launch_knn(0, points_1, rs1, points_2, rs2);
        mma_gemm_kernel<COUT><<<gg1, 256, SM_TOT>>>(
            x1hi, x1lo, w1hi, b1, g1, be1, m1, v1, out);
        interp_add_kernel<<<gia, 256>>>(out);
    }
}